// round 9
// baseline (speedup 1.0000x reference)
#include <cuda_runtime.h>
#include <cuda_bf16.h>
#include <math.h>
#include <float.h>

#define NMAX 20000
#define EMAX 200000

typedef unsigned long long ull;
typedef unsigned int u32;
typedef __nv_bfloat16 bf16;

// ---------------- scratch (device globals; no allocation allowed) ----------
__device__ float g_bufA[NMAX * 512];          // xl (fp32, GEMM out for GAT layers)
__device__ float g_s[NMAX * 8];
__device__ float g_d[NMAX * 8];
__device__ int   g_xpi[EMAX * 6];
__device__ float g_xp2[EMAX * 512];
__device__ int g_degA[NMAX], g_degL[NMAX], g_degR[NMAX];
__device__ int g_rowA[NMAX + 1], g_rowL[NMAX + 1], g_rowR[NMAX + 1];
__device__ int g_curA[NMAX], g_curL[NMAX], g_curR[NMAX];
__device__ int g_adjA[EMAX + NMAX];
__device__ int g_eidL[EMAX], g_eidR[EMAX];
// split activation pairs (bf16 hi/lo)
__device__ bf16 g_xph[NMAX * 128],  g_xpl[NMAX * 128];
__device__ bf16 g_h1h[EMAX * 256],  g_h1l[EMAX * 256];
__device__ bf16 g_x1h[NMAX * 512],  g_x1l[NMAX * 512];
__device__ bf16 g_finh[NMAX * 1536], g_finl[NMAX * 1536];
__device__ bf16 g_hch[NMAX * 512],  g_hcl[NMAX * 512];
// bf16 split weights, transposed to [N][K]
__device__ bf16 g_w1h[512 * 128],  g_w1l[512 * 128];
__device__ bf16 g_w2h[512 * 512],  g_w2l[512 * 512];
__device__ bf16 g_we2h[512 * 256], g_we2l[512 * 256];
__device__ bf16 g_wc1h[512 * 1536], g_wc1l[512 * 1536];
__device__ bf16 g_wc2h[256 * 512], g_wc2l[256 * 512];

// ---------------- PTX helpers (baseline ISA only) ----------------------------
__device__ __forceinline__ u32 smem_u32(const void* p) {
    u32 a;
    asm("{ .reg .u64 t; cvta.to.shared.u64 t, %1; cvt.u32.u64 %0, t; }" : "=r"(a) : "l"(p));
    return a;
}
#define LDSM4(r, addr) \
    asm volatile("ldmatrix.sync.aligned.m8n8.x4.shared.b16 {%0,%1,%2,%3}, [%4];" \
        : "=r"((r)[0]), "=r"((r)[1]), "=r"((r)[2]), "=r"((r)[3]) : "r"(addr))
#define MMA16816(c, a, b0, b1) \
    asm volatile("mma.sync.aligned.m16n8k16.row.col.f32.bf16.bf16.f32 " \
        "{%0,%1,%2,%3}, {%4,%5,%6,%7}, {%8,%9}, {%0,%1,%2,%3};" \
        : "+f"((c)[0]), "+f"((c)[1]), "+f"((c)[2]), "+f"((c)[3]) \
        : "r"((a)[0]), "r"((a)[1]), "r"((a)[2]), "r"((a)[3]), "r"(b0), "r"(b1))
#define CP_ASYNC16(s, g) \
    asm volatile("cp.async.ca.shared.global [%0], [%1], 16;" :: "r"(s), "l"(g))
#define CP_ASYNC16Z(s, g, sz) \
    asm volatile("cp.async.ca.shared.global [%0], [%1], 16, %2;" :: "r"(s), "l"(g), "r"(sz))
#define CP_COMMIT() asm volatile("cp.async.commit_group;" ::: "memory")
#define CP_WAIT0()  asm volatile("cp.async.wait_group 0;" ::: "memory")
#define CP_WAIT1()  asm volatile("cp.async.wait_group 1;" ::: "memory")

// pack (bf16(x),bf16(y)) and residual pair
__device__ __forceinline__ void split2(float x, float y, u32& hi, u32& lo) {
    __nv_bfloat162 h = __floats2bfloat162_rn(x, y);
    float hx = __bfloat162float(__low2bfloat16(h));
    float hy = __bfloat162float(__high2bfloat16(h));
    __nv_bfloat162 l = __floats2bfloat162_rn(x - hx, y - hy);
    hi = *reinterpret_cast<u32*>(&h);
    lo = *reinterpret_cast<u32*>(&l);
}
__device__ __forceinline__ void split1(float v, bf16& h, bf16& l) {
    h = __float2bfloat16(v);
    l = __float2bfloat16(v - __bfloat162float(h));
}

// ---------------- monotonic float<->int for atomicMax ----------------------
__device__ __forceinline__ int mono_enc(float f) {
    int i = __float_as_int(f);
    return i >= 0 ? i : (i ^ 0x7FFFFFFF);
}
__device__ __forceinline__ float mono_dec(int i) {
    int j = i >= 0 ? i : (i ^ 0x7FFFFFFF);
    return __int_as_float(j);
}

// ---------------- tiny utility kernels -------------------------------------
__global__ void fill_int(int* p, int v, int n) {
    int i = blockIdx.x * blockDim.x + threadIdx.x;
    if (i < n) p[i] = v;
}

// W[K,Nsrc] -> Wh/Wl[N][K] bf16 split (pad cols Nsrc..N-1 with 0)
__global__ void prep_w(const float* __restrict__ W, bf16* __restrict__ Wh,
                       bf16* __restrict__ Wl, int K, int N, int Nsrc) {
    long long i = (long long)blockIdx.x * 256 + threadIdx.x;
    if (i >= (long long)N * K) return;
    int n = (int)(i / K), k = (int)(i - (long long)n * K);
    float v = (n < Nsrc) ? W[(size_t)k * Nsrc + n] : 0.f;
    bf16 h, l;
    split1(v, h, l);
    Wh[i] = h; Wl[i] = l;
}

// X fp32 -> (Xh, Xl) split, 2 elements per thread
__global__ void split_f32(const float* __restrict__ X, bf16* __restrict__ Xh,
                          bf16* __restrict__ Xl, long long n) {
    long long i = ((long long)blockIdx.x * 256 + threadIdx.x) * 2;
    if (i >= n) return;
    u32 h, l;
    split2(X[i], X[i + 1], h, l);
    *(u32*)(Xh + i) = h;
    *(u32*)(Xl + i) = l;
}

// h1 = relu(decode(xpi) @ We1 + be1), written as split bf16 pair. 2 cols/thread.
__global__ void mlp1_split(const int* __restrict__ xpi, const float* __restrict__ We1,
                           const float* __restrict__ be1, bf16* __restrict__ h1h,
                           bf16* __restrict__ h1l, int E) {
    long long idx = (long long)blockIdx.x * 256 + threadIdx.x;
    if (idx >= (long long)E * 128) return;
    int r = (int)(idx >> 7), c2 = ((int)idx & 127) << 1;
    float x0 = mono_dec(__ldg(&xpi[r * 6 + 0]));
    float x1 = mono_dec(__ldg(&xpi[r * 6 + 1]));
    float x2 = mono_dec(__ldg(&xpi[r * 6 + 2]));
    float x3 = mono_dec(__ldg(&xpi[r * 6 + 3]));
    float x4 = mono_dec(__ldg(&xpi[r * 6 + 4]));
    float x5 = mono_dec(__ldg(&xpi[r * 6 + 5]));
    float v[2];
#pragma unroll
    for (int j = 0; j < 2; j++) {
        int kk = c2 + j;
        float t = __ldg(&be1[kk])
                + x0 * __ldg(&We1[kk])        + x1 * __ldg(&We1[256 + kk])
                + x2 * __ldg(&We1[512 + kk])  + x3 * __ldg(&We1[768 + kk])
                + x4 * __ldg(&We1[1024 + kk]) + x5 * __ldg(&We1[1280 + kk]);
        v[j] = fmaxf(t, 0.f);
    }
    u32 h, l;
    split2(v[0], v[1], h, l);
    *(u32*)(h1h + (size_t)r * 256 + c2) = h;
    *(u32*)(h1l + (size_t)r * 256 + c2) = l;
}

// ---------------- CSR build -------------------------------------------------
__global__ void count_deg(const int* __restrict__ ei, int E, int n,
                          int* degA, int* degL, int* degR) {
    int e = blockIdx.x * blockDim.x + threadIdx.x;
    if (e < E) {
        int s = ei[e], d = ei[E + e];
        atomicAdd(&degA[d], 1);
        atomicAdd(&degL[s], 1);
        atomicAdd(&degR[d], 1);
    } else if (e < E + n) {
        atomicAdd(&degA[e - E], 1);
    }
}

__global__ void scan3_kernel(const int* dA, int* rA, int* cA,
                             const int* dL, int* rL, int* cL,
                             const int* dR, int* rR, int* cR, int n) {
    const int* deg = blockIdx.x == 0 ? dA : (blockIdx.x == 1 ? dL : dR);
    int* rowoff    = blockIdx.x == 0 ? rA : (blockIdx.x == 1 ? rL : rR);
    int* cur       = blockIdx.x == 0 ? cA : (blockIdx.x == 1 ? cL : cR);
    __shared__ int sh[1024];
    __shared__ int carry;
    int tid = threadIdx.x;
    if (tid == 0) carry = 0;
    __syncthreads();
    for (int base = 0; base < n; base += 1024) {
        int i = base + tid;
        int v = (i < n) ? deg[i] : 0;
        sh[tid] = v;
        __syncthreads();
        for (int off = 1; off < 1024; off <<= 1) {
            int t = (tid >= off) ? sh[tid - off] : 0;
            __syncthreads();
            sh[tid] += t;
            __syncthreads();
        }
        int excl = sh[tid] - v + carry;
        if (i < n) { rowoff[i] = excl; cur[i] = excl; }
        __syncthreads();
        if (tid == 1023) carry += sh[1023];
        __syncthreads();
    }
    if (tid == 0) rowoff[n] = carry;
}

__global__ void fill_adj(const int* __restrict__ ei, int E, int n,
                         int* curA, int* adjA, int* curL, int* eidL,
                         int* curR, int* eidR) {
    int e = blockIdx.x * blockDim.x + threadIdx.x;
    if (e < E) {
        int s = ei[e], d = ei[E + e];
        int p = atomicAdd(&curA[d], 1); adjA[p] = s;
        p = atomicAdd(&curL[s], 1); eidL[p] = e;
        p = atomicAdd(&curR[d], 1); eidR[p] = e;
    } else if (e < E + n) {
        int node = e - E;
        int p = atomicAdd(&curA[node], 1); adjA[p] = node;
    }
}

// ---------------- mma.sync GEMM (3-stage cp.async, pre-split operands) -------
// C[M,N] = act(A @ W + bias); A given as split pair [M][K], W as split [N][K].
// 128x128 CTA tile, 8 warps of 32x64, BK=32, 3 stages, 1 sync per chunk.
// OUT_SPLIT==1: write (Ch, Cl) split bf16 instead of fp32 C (N must be full tiles).
#define APITCH 40
#define STAGE_BYTES 40960
template<int OUT_SPLIT>
__global__ __launch_bounds__(256)
void mma_gemm(const bf16* __restrict__ Ah, const bf16* __restrict__ Al,
              const bf16* __restrict__ Bh, const bf16* __restrict__ Bl,
              const float* __restrict__ bias, float* __restrict__ C,
              bf16* __restrict__ Ch, bf16* __restrict__ Cl,
              int M, int N, int K, int Cld, int Nstore, int act) {
    extern __shared__ char dsm[];
    const u32 dbase = (smem_u32(dsm) + 127) & ~127u;
    const int tid = threadIdx.x, lane = tid & 31, wid = tid >> 5;
    const int mwarp = wid & 3, nwarp = wid >> 2;
    const int blockRow = blockIdx.y * 128, blockCol = blockIdx.x * 128;

    float acc[2][8][4];
#pragma unroll
    for (int m = 0; m < 2; m++)
#pragma unroll
        for (int n = 0; n < 8; n++)
#pragma unroll
            for (int j = 0; j < 4; j++) acc[m][n][j] = 0.f;

    const int nch = K >> 5;

    auto issue = [&](int c, int st) {
        int k0 = c << 5;
        u32 sb = dbase + st * STAGE_BYTES;
        // A hi/lo (rows may exceed M -> zfill)
#pragma unroll
        for (int l = 0; l < 4; l++) {
            int idx = tid + l * 256;
            int arr = idx >> 9, rem = idx & 511, row = rem >> 2, seg = rem & 3;
            int gr = blockRow + row;
            u32 sz = 16;
            if (gr >= M) { gr = 0; sz = 0; }
            const bf16* gsrc = (arr ? Al : Ah) + (size_t)gr * K + k0 + seg * 8;
            u32 sdst = sb + arr * 10240 + (row * APITCH + seg * 8) * 2;
            CP_ASYNC16Z(sdst, gsrc, sz);
        }
        // B hi/lo (always in-bounds)
#pragma unroll
        for (int l = 0; l < 4; l++) {
            int idx = tid + l * 256;
            int arr = idx >> 9, rem = idx & 511, row = rem >> 2, seg = rem & 3;
            const bf16* gsrc = (arr ? Bl : Bh) + (size_t)(blockCol + row) * K + k0 + seg * 8;
            u32 sdst = sb + (arr ? 30720 : 20480) + (row * APITCH + seg * 8) * 2;
            CP_ASYNC16(sdst, gsrc);
        }
        CP_COMMIT();
    };
    auto compute = [&](int st) {
        u32 sb = dbase + st * STAGE_BYTES;
        u32 Ah_ = sb, Al_ = sb + 10240, Bh_ = sb + 20480, Bl_ = sb + 30720;
        int arow = 32 * mwarp + (lane & 15);
        int acol = (lane >> 4) * 8;
        int brow = (lane & 7) + ((lane >> 4) << 3);
        int bcol = ((lane >> 3) & 1) * 8;
#pragma unroll
        for (int ks = 0; ks < 2; ks++) {
            int koff = ks * 16;
            u32 ah[2][4], al[2][4];
#pragma unroll
            for (int m = 0; m < 2; m++) {
                u32 ao = ((arow + m * 16) * APITCH + acol + koff) * 2;
                LDSM4(ah[m], Ah_ + ao);
                LDSM4(al[m], Al_ + ao);
            }
#pragma unroll
            for (int p = 0; p < 4; p++) {
                int n0 = 64 * nwarp + p * 16;
                u32 bo = ((n0 + brow) * APITCH + bcol + koff) * 2;
                u32 bh[4], bl[4];
                LDSM4(bh, Bh_ + bo);
                LDSM4(bl, Bl_ + bo);
#pragma unroll
                for (int m = 0; m < 2; m++) {
                    MMA16816(acc[m][2 * p],     ah[m], bh[0], bh[1]);
                    MMA16816(acc[m][2 * p],     ah[m], bl[0], bl[1]);
                    MMA16816(acc[m][2 * p],     al[m], bh[0], bh[1]);
                    MMA16816(acc[m][2 * p + 1], ah[m], bh[2], bh[3]);
                    MMA16816(acc[m][2 * p + 1], ah[m], bl[2], bl[3]);
                    MMA16816(acc[m][2 * p + 1], al[m], bh[2], bh[3]);
                }
            }
        }
    };

    // 3-stage pipeline, one barrier per chunk.
    issue(0, 0);
    issue(1, 1);
    for (int c = 0; c < nch; c++) {
        if (c + 1 < nch) { CP_WAIT1(); } else { CP_WAIT0(); }
        __syncthreads();
        if (c + 2 < nch) issue(c + 2, (c + 2) % 3);
        compute(c % 3);
    }

    // ---- epilogue ----
    int g = lane >> 2, t = lane & 3;
#pragma unroll
    for (int m = 0; m < 2; m++) {
        int row0 = blockRow + 32 * mwarp + m * 16 + g;
#pragma unroll
        for (int nt = 0; nt < 8; nt++) {
            int col0 = blockCol + 64 * nwarp + nt * 8 + t * 2;
#pragma unroll
            for (int half = 0; half < 2; half++) {
                int r = row0 + half * 8;
                if (r >= M) continue;
                float v0 = acc[m][nt][half * 2 + 0];
                float v1 = acc[m][nt][half * 2 + 1];
                if (bias) { v0 += bias[col0]; v1 += bias[col0 + 1]; }
                if (act) { v0 = fmaxf(v0, 0.f); v1 = fmaxf(v1, 0.f); }
                if constexpr (OUT_SPLIT) {
                    u32 h, l;
                    split2(v0, v1, h, l);
                    *(u32*)(Ch + (size_t)r * Cld + col0) = h;
                    *(u32*)(Cl + (size_t)r * Cld + col0) = l;
                } else {
                    if (col0 < Nstore)     C[(size_t)r * Cld + col0] = v0;
                    if (col0 + 1 < Nstore) C[(size_t)r * Cld + col0 + 1] = v1;
                }
            }
        }
    }
}

// ---------------- GAT attention scalars -------------------------------------
__global__ void sd_kernel(const float* __restrict__ xl, const float* __restrict__ asr,
                          const float* __restrict__ adt, float* __restrict__ s,
                          float* __restrict__ d, int n, int H, int C) {
    int warp = (blockIdx.x * blockDim.x + threadIdx.x) >> 5;
    int lane = threadIdx.x & 31;
    if (warp >= n * H) return;
    int node = warp / H, h = warp - node * H;
    const float* row = xl + (size_t)node * H * C + (size_t)h * C;
    float ss = 0.f, dd = 0.f;
    for (int c = lane; c < C; c += 32) {
        float v = row[c];
        ss += v * asr[h * C + c];
        dd += v * adt[h * C + c];
    }
#pragma unroll
    for (int o = 16; o; o >>= 1) {
        ss += __shfl_down_sync(~0u, ss, o);
        dd += __shfl_down_sync(~0u, dd, o);
    }
    if (!lane) { s[warp] = ss; d[warp] = dd; }
}

// ---------------- GAT aggregation (CSR, atomic-free, split bf16 output) -----
template<int H, int C>
__launch_bounds__(256)
__global__ void gat_agg(const int* __restrict__ row, const int* __restrict__ adj,
                        const float* __restrict__ s, const float* __restrict__ dvec,
                        const float* __restrict__ xl, const float* __restrict__ bias,
                        bf16* __restrict__ outh, bf16* __restrict__ outl,
                        int ldout, int doElu) {
    constexpr int HC = H * C;
    constexpr int CAP = 512;
    constexpr int PT = (HC + 255) / 256;
    __shared__ float al[CAP * H];
    __shared__ int asrc[CAP];
    __shared__ float mh[8], zinv[8];

    int n = blockIdx.x, tid = threadIdx.x, w = tid >> 5, lane = tid & 31;
    int start = row[n], deg = row[n + 1] - start;

    if (w < H) {
        float dh = dvec[n * H + w];
        float m = -FLT_MAX;
        for (int i = lane; i < deg; i += 32) {
            float a = s[adj[start + i] * H + w] + dh;
            a = a > 0.f ? a : 0.2f * a;
            m = fmaxf(m, a);
        }
#pragma unroll
        for (int o = 16; o; o >>= 1) m = fmaxf(m, __shfl_xor_sync(~0u, m, o));
        float z = 0.f;
        for (int i = lane; i < deg; i += 32) {
            float a = s[adj[start + i] * H + w] + dh;
            a = a > 0.f ? a : 0.2f * a;
            z += expf(a - m);
        }
#pragma unroll
        for (int o = 16; o; o >>= 1) z += __shfl_xor_sync(~0u, z, o);
        if (lane == 0) { mh[w] = m; zinv[w] = 1.f / (z + 1e-16f); }
    }
    __syncthreads();

    float acc[PT];
#pragma unroll
    for (int p = 0; p < PT; p++) {
        int c = tid + p * 256;
        acc[p] = (c < HC) ? bias[c] : 0.f;
    }

    for (int base = 0; base < deg; base += CAP) {
        int cnt = min(CAP, deg - base);
        __syncthreads();
        for (int i = tid; i < cnt; i += 256) asrc[i] = adj[start + base + i];
        __syncthreads();
        for (int i = tid; i < cnt * H; i += 256) {
            int e = i / H, h = i - e * H;
            float a = s[asrc[e] * H + h] + dvec[n * H + h];
            a = a > 0.f ? a : 0.2f * a;
            al[e * H + h] = expf(a - mh[h]) * zinv[h];
        }
        __syncthreads();
#pragma unroll
        for (int p = 0; p < PT; p++) {
            int c = tid + p * 256;
            if (c < HC) {
                int h = c / C;
                float a = acc[p];
                for (int i = 0; i < cnt; i++)
                    a += al[i * H + h] * xl[(size_t)asrc[i] * HC + c];
                acc[p] = a;
            }
        }
    }

#pragma unroll
    for (int p = 0; p < PT; p++) {
        int c = tid + p * 256;
        if (c < HC) {
            float v = acc[p];
            if (doElu) v = v > 0.f ? v : expm1f(v);
            bf16 h, l;
            split1(v, h, l);
            outh[(size_t)n * ldout + c] = h;
            outl[(size_t)n * ldout + c] = l;
        }
    }
}

// ---------------- merged scatter-mean (L and R in one launch) ----------------
__launch_bounds__(256)
__global__ void mean_gather2(const int* __restrict__ rowL, const int* __restrict__ eidL,
                             const int* __restrict__ rowR, const int* __restrict__ eidR,
                             const float* __restrict__ xp2, bf16* __restrict__ finh,
                             bf16* __restrict__ finl) {
    __shared__ int eids[512];
    int n = blockIdx.x, tid = threadIdx.x;
#pragma unroll
    for (int side = 0; side < 2; side++) {
        const int* row = side ? rowR : rowL;
        const int* eid = side ? eidR : eidL;
        int off = side ? 1024 : 512;
        int start = row[n], deg = row[n + 1] - start;
        float a0 = 0.f, a1 = 0.f;
        for (int base = 0; base < deg; base += 512) {
            int cnt = min(512, deg - base);
            __syncthreads();
            for (int i = tid; i < cnt; i += 256) eids[i] = eid[start + base + i];
            __syncthreads();
            for (int i = 0; i < cnt; i++) {
                const float* r = xp2 + (size_t)eids[i] * 512;
                a0 += r[tid];
                a1 += r[tid + 256];
            }
        }
        float inv = 1.f / fmaxf((float)deg, 1.f);
        a0 *= inv; a1 *= inv;
        bf16 h, l;
        split1(a0, h, l);
        finh[(size_t)n * 1536 + off + tid] = h;
        finl[(size_t)n * 1536 + off + tid] = l;
        split1(a1, h, l);
        finh[(size_t)n * 1536 + off + tid + 256] = h;
        finl[(size_t)n * 1536 + off + tid + 256] = l;
        __syncthreads();
    }
}

// ---------------- synapse max-pool ------------------------------------------
__global__ void synapse_max(const float* __restrict__ syn, const int* __restrict__ sidx,
                            int* __restrict__ xpi, int P) {
    int idx = blockIdx.x * blockDim.x + threadIdx.x;
    if (idx >= P * 6) return;
    int p = idx / 6, f = idx - p * 6;
    atomicMax(&xpi[(size_t)sidx[p] * 6 + f], mono_enc(syn[(size_t)p * 6 + f]));
}

// ---------------- host ------------------------------------------------------
static inline int g1(long long total) { return (int)((total + 255) / 256); }
#define GEMM_DSM (3 * STAGE_BYTES + 128)

extern "C" void kernel_launch(void* const* d_in, const int* in_sizes, int n_in,
                              void* d_out, int out_size) {
    const int*   ei   = (const int*)d_in[0];
    const float* syn  = (const float*)d_in[2];
    const int*   sidx = (const int*)d_in[3];
    const float* x_p  = (const float*)d_in[5];
    const float* W1   = (const float*)d_in[6];
    const float* as1  = (const float*)d_in[7];
    const float* ad1  = (const float*)d_in[8];
    const float* b1   = (const float*)d_in[9];
    const float* W2   = (const float*)d_in[10];
    const float* as2  = (const float*)d_in[11];
    const float* ad2  = (const float*)d_in[12];
    const float* b2   = (const float*)d_in[13];
    const float* We1  = (const float*)d_in[14];
    const float* be1  = (const float*)d_in[15];
    const float* We2  = (const float*)d_in[16];
    const float* be2  = (const float*)d_in[17];
    const float* Wc1  = (const float*)d_in[18];
    const float* bc1  = (const float*)d_in[19];
    const float* Wc2  = (const float*)d_in[20];
    const float* bc2  = (const float*)d_in[21];

    const int E = in_sizes[0] / 2;
    const int P = in_sizes[2] / 6;
    const int N = in_sizes[5] / 128;
    const int NCLS = in_sizes[20] / 512;
    float* out = (float*)d_out;

    float *bufA, *s, *d, *xp2;
    int *xpi, *degA, *degL, *degR, *rowA, *rowL, *rowR, *curA, *curL, *curR,
        *adjA, *eidL, *eidR;
    bf16 *xph, *xpl, *h1h, *h1l, *x1h, *x1l, *finh, *finl, *hch, *hcl;
    bf16 *w1h, *w1l, *w2h, *w2l, *we2h, *we2l, *wc1h, *wc1l, *wc2h, *wc2l;
    cudaGetSymbolAddress((void**)&bufA, g_bufA);
    cudaGetSymbolAddress((void**)&s,    g_s);
    cudaGetSymbolAddress((void**)&d,    g_d);
    cudaGetSymbolAddress((void**)&xpi,  g_xpi);
    cudaGetSymbolAddress((void**)&xp2,  g_xp2);
    cudaGetSymbolAddress((void**)&degA, g_degA);
    cudaGetSymbolAddress((void**)&degL, g_degL);
    cudaGetSymbolAddress((void**)&degR, g_degR);
    cudaGetSymbolAddress((void**)&rowA, g_rowA);
    cudaGetSymbolAddress((void**)&rowL, g_rowL);
    cudaGetSymbolAddress((void**)&rowR, g_rowR);
    cudaGetSymbolAddress((void**)&curA, g_curA);
    cudaGetSymbolAddress((void**)&curL, g_curL);
    cudaGetSymbolAddress((void**)&curR, g_curR);
    cudaGetSymbolAddress((void**)&adjA, g_adjA);
    cudaGetSymbolAddress((void**)&eidL, g_eidL);
    cudaGetSymbolAddress((void**)&eidR, g_eidR);
    cudaGetSymbolAddress((void**)&xph, g_xph);  cudaGetSymbolAddress((void**)&xpl, g_xpl);
    cudaGetSymbolAddress((void**)&h1h, g_h1h);  cudaGetSymbolAddress((void**)&h1l, g_h1l);
    cudaGetSymbolAddress((void**)&x1h, g_x1h);  cudaGetSymbolAddress((void**)&x1l, g_x1l);
    cudaGetSymbolAddress((void**)&finh, g_finh); cudaGetSymbolAddress((void**)&finl, g_finl);
    cudaGetSymbolAddress((void**)&hch, g_hch);  cudaGetSymbolAddress((void**)&hcl, g_hcl);
    cudaGetSymbolAddress((void**)&w1h, g_w1h);  cudaGetSymbolAddress((void**)&w1l, g_w1l);
    cudaGetSymbolAddress((void**)&w2h, g_w2h);  cudaGetSymbolAddress((void**)&w2l, g_w2l);
    cudaGetSymbolAddress((void**)&we2h, g_we2h); cudaGetSymbolAddress((void**)&we2l, g_we2l);
    cudaGetSymbolAddress((void**)&wc1h, g_wc1h); cudaGetSymbolAddress((void**)&wc1l, g_wc1l);
    cudaGetSymbolAddress((void**)&wc2h, g_wc2h); cudaGetSymbolAddress((void**)&wc2l, g_wc2l);

    cudaFuncSetAttribute(mma_gemm<0>, cudaFuncAttributeMaxDynamicSharedMemorySize, GEMM_DSM);
    cudaFuncSetAttribute(mma_gemm<1>, cudaFuncAttributeMaxDynamicSharedMemorySize, GEMM_DSM);

    // ===== synapse branch first (puts the big GEMM at launch index 5 for ncu) =====
    fill_int<<<g1((long long)E * 6), 256>>>(xpi, 0x80800000, E * 6);          // 0
    synapse_max<<<g1((long long)P * 6), 256>>>(syn, sidx, xpi, P);            // 1
    mlp1_split<<<g1((long long)E * 128), 256>>>(xpi, We1, be1, h1h, h1l, E);  // 2
    prep_w<<<g1(512LL * 256), 256>>>(We2, we2h, we2l, 256, 512, 512);         // 3
    split_f32<<<g1((long long)N * 64), 256>>>(x_p, xph, xpl, (long long)N * 128); // 4
    {
        dim3 g(4, (E + 127) / 128);                                           // 5 <- ncu
        mma_gemm<0><<<g, 256, GEMM_DSM>>>(h1h, h1l, we2h, we2l, be2, xp2,
                                          nullptr, nullptr, E, 512, 256, 512, 512, 0);
    }

    // ===== remaining weight prep =====
    prep_w<<<g1(512LL * 128), 256>>>(W1, w1h, w1l, 128, 512, 512);
    prep_w<<<g1(512LL * 512), 256>>>(W2, w2h, w2l, 512, 512, 512);
    prep_w<<<g1(512LL * 1536), 256>>>(Wc1, wc1h, wc1l, 1536, 512, 512);
    prep_w<<<g1(256LL * 512), 256>>>(Wc2, wc2h, wc2l, 512, 256, NCLS);

    // ===== CSR build =====
    fill_int<<<g1(N), 256>>>(degA, 0, N);
    fill_int<<<g1(N), 256>>>(degL, 0, N);
    fill_int<<<g1(N), 256>>>(degR, 0, N);
    count_deg<<<g1(E + N), 256>>>(ei, E, N, degA, degL, degR);
    scan3_kernel<<<3, 1024>>>(degA, rowA, curA, degL, rowL, curL, degR, rowR, curR, N);
    fill_adj<<<g1(E + N), 256>>>(ei, E, N, curA, adjA, curL, eidL, curR, eidR);

    // ===== GAT layer 1 =====
    {
        dim3 g(4, (N + 127) / 128);
        mma_gemm<0><<<g, 256, GEMM_DSM>>>(xph, xpl, w1h, w1l, nullptr, bufA,
                                          nullptr, nullptr, N, 512, 128, 512, 512, 0);
    }
    sd_kernel<<<g1((long long)N * 8 * 32), 256>>>(bufA, as1, ad1, s, d, N, 8, 64);
    gat_agg<8, 64><<<N, 256>>>(rowA, adjA, s, d, bufA, b1, x1h, x1l, 512, 1);

    // ===== GAT layer 2 =====
    {
        dim3 g(4, (N + 127) / 128);
        mma_gemm<0><<<g, 256, GEMM_DSM>>>(x1h, x1l, w2h, w2l, nullptr, bufA,
                                          nullptr, nullptr, N, 512, 512, 512, 512, 0);
    }
    sd_kernel<<<g1((long long)N * 32), 256>>>(bufA, as2, ad2, s, d, N, 1, 512);
    gat_agg<1, 512><<<N, 256>>>(rowA, adjA, s, d, bufA, b2, finh, finl, 1536, 0);

    // ===== scatter means into fin[:,512:1536] =====
    mean_gather2<<<N, 256>>>(rowL, eidL, rowR, eidR, xp2, finh, finl);

    // ===== classifier =====
    {
        dim3 g(4, (N + 127) / 128);
        mma_gemm<1><<<g, 256, GEMM_DSM>>>(finh, finl, wc1h, wc1l, bc1, nullptr,
                                          hch, hcl, N, 512, 1536, 512, 512, 1);
    }
    {
        dim3 g(2, (N + 127) / 128);
        mma_gemm<0><<<g, 256, GEMM_DSM>>>(hch, hcl, wc2h, wc2l, bc2, out,
                                          nullptr, nullptr, N, 256, 512, NCLS, NCLS, 0);
    }
}

// round 11
// speedup vs baseline: 1.1447x; 1.1447x over previous
#include <cuda_runtime.h>
#include <cuda_bf16.h>
#include <math.h>
#include <float.h>

#define NMAX 20000
#define EMAX 200000

typedef unsigned long long ull;
typedef unsigned int u32;
typedef __nv_bfloat16 bf16;

// ---------------- scratch (device globals; no allocation allowed) ----------
__device__ float g_bufA[NMAX * 512];          // xl (fp32, GEMM out for GAT layers)
__device__ float g_s[NMAX * 8];
__device__ float g_d[NMAX * 8];
__device__ int   g_xpi[EMAX * 6];
__device__ float g_xp2[EMAX * 512];
__device__ int g_degA[NMAX], g_degL[NMAX], g_degR[NMAX];
__device__ int g_rowA[NMAX + 1], g_rowL[NMAX + 1], g_rowR[NMAX + 1];
__device__ int g_curA[NMAX], g_curL[NMAX], g_curR[NMAX];
__device__ int g_adjA[EMAX + NMAX];
__device__ int g_eidL[EMAX], g_eidR[EMAX];
// split activation pairs (bf16 hi/lo)
__device__ bf16 g_xph[NMAX * 128],  g_xpl[NMAX * 128];
__device__ bf16 g_h1h[EMAX * 256],  g_h1l[EMAX * 256];
__device__ bf16 g_x1h[NMAX * 512],  g_x1l[NMAX * 512];
__device__ bf16 g_finh[NMAX * 1536], g_finl[NMAX * 1536];
__device__ bf16 g_hch[NMAX * 512],  g_hcl[NMAX * 512];
// bf16 split weights, transposed to [N][K]
__device__ bf16 g_w1h[512 * 128],  g_w1l[512 * 128];
__device__ bf16 g_w2h[512 * 512],  g_w2l[512 * 512];
__device__ bf16 g_we2h[512 * 256], g_we2l[512 * 256];
__device__ bf16 g_wc1h[512 * 1536], g_wc1l[512 * 1536];
__device__ bf16 g_wc2h[256 * 512], g_wc2l[256 * 512];

// ---------------- PTX helpers (baseline ISA only) ----------------------------
__device__ __forceinline__ u32 smem_u32(const void* p) {
    u32 a;
    asm("{ .reg .u64 t; cvta.to.shared.u64 t, %1; cvt.u32.u64 %0, t; }" : "=r"(a) : "l"(p));
    return a;
}
#define LDSM4(r, addr) \
    asm volatile("ldmatrix.sync.aligned.m8n8.x4.shared.b16 {%0,%1,%2,%3}, [%4];" \
        : "=r"((r)[0]), "=r"((r)[1]), "=r"((r)[2]), "=r"((r)[3]) : "r"(addr))
#define MMA16816(c, a, b0, b1) \
    asm volatile("mma.sync.aligned.m16n8k16.row.col.f32.bf16.bf16.f32 " \
        "{%0,%1,%2,%3}, {%4,%5,%6,%7}, {%8,%9}, {%0,%1,%2,%3};" \
        : "+f"((c)[0]), "+f"((c)[1]), "+f"((c)[2]), "+f"((c)[3]) \
        : "r"((a)[0]), "r"((a)[1]), "r"((a)[2]), "r"((a)[3]), "r"(b0), "r"(b1))
#define CP_ASYNC16(s, g) \
    asm volatile("cp.async.ca.shared.global [%0], [%1], 16;" :: "r"(s), "l"(g))
#define CP_ASYNC16Z(s, g, sz) \
    asm volatile("cp.async.ca.shared.global [%0], [%1], 16, %2;" :: "r"(s), "l"(g), "r"(sz))
#define CP_COMMIT() asm volatile("cp.async.commit_group;" ::: "memory")
#define CP_WAIT0()  asm volatile("cp.async.wait_group 0;" ::: "memory")
#define CP_WAIT1()  asm volatile("cp.async.wait_group 1;" ::: "memory")

// pack (bf16(x),bf16(y)) and residual pair
__device__ __forceinline__ void split2(float x, float y, u32& hi, u32& lo) {
    __nv_bfloat162 h = __floats2bfloat162_rn(x, y);
    float hx = __bfloat162float(__low2bfloat16(h));
    float hy = __bfloat162float(__high2bfloat16(h));
    __nv_bfloat162 l = __floats2bfloat162_rn(x - hx, y - hy);
    hi = *reinterpret_cast<u32*>(&h);
    lo = *reinterpret_cast<u32*>(&l);
}
__device__ __forceinline__ void split1(float v, bf16& h, bf16& l) {
    h = __float2bfloat16(v);
    l = __float2bfloat16(v - __bfloat162float(h));
}

// ---------------- monotonic float<->int for atomicMax ----------------------
__device__ __forceinline__ int mono_enc(float f) {
    int i = __float_as_int(f);
    return i >= 0 ? i : (i ^ 0x7FFFFFFF);
}
__device__ __forceinline__ float mono_dec(int i) {
    int j = i >= 0 ? i : (i ^ 0x7FFFFFFF);
    return __int_as_float(j);
}

// ---------------- tiny utility kernels -------------------------------------
__global__ void fill_int(int* p, int v, int n) {
    int i = blockIdx.x * blockDim.x + threadIdx.x;
    if (i < n) p[i] = v;
}

// W[K,Nsrc] -> Wh/Wl[N][K] bf16 split (pad cols Nsrc..N-1 with 0)
__global__ void prep_w(const float* __restrict__ W, bf16* __restrict__ Wh,
                       bf16* __restrict__ Wl, int K, int N, int Nsrc) {
    long long i = (long long)blockIdx.x * 256 + threadIdx.x;
    if (i >= (long long)N * K) return;
    int n = (int)(i / K), k = (int)(i - (long long)n * K);
    float v = (n < Nsrc) ? W[(size_t)k * Nsrc + n] : 0.f;
    bf16 h, l;
    split1(v, h, l);
    Wh[i] = h; Wl[i] = l;
}

// X fp32 -> (Xh, Xl) split, 2 elements per thread
__global__ void split_f32(const float* __restrict__ X, bf16* __restrict__ Xh,
                          bf16* __restrict__ Xl, long long n) {
    long long i = ((long long)blockIdx.x * 256 + threadIdx.x) * 2;
    if (i >= n) return;
    u32 h, l;
    split2(X[i], X[i + 1], h, l);
    *(u32*)(Xh + i) = h;
    *(u32*)(Xl + i) = l;
}

// h1 = relu(decode(xpi) @ We1 + be1), written as split bf16 pair. 2 cols/thread.
__global__ void mlp1_split(const int* __restrict__ xpi, const float* __restrict__ We1,
                           const float* __restrict__ be1, bf16* __restrict__ h1h,
                           bf16* __restrict__ h1l, int E) {
    long long idx = (long long)blockIdx.x * 256 + threadIdx.x;
    if (idx >= (long long)E * 128) return;
    int r = (int)(idx >> 7), c2 = ((int)idx & 127) << 1;
    float x0 = mono_dec(__ldg(&xpi[r * 6 + 0]));
    float x1 = mono_dec(__ldg(&xpi[r * 6 + 1]));
    float x2 = mono_dec(__ldg(&xpi[r * 6 + 2]));
    float x3 = mono_dec(__ldg(&xpi[r * 6 + 3]));
    float x4 = mono_dec(__ldg(&xpi[r * 6 + 4]));
    float x5 = mono_dec(__ldg(&xpi[r * 6 + 5]));
    float v[2];
#pragma unroll
    for (int j = 0; j < 2; j++) {
        int kk = c2 + j;
        float t = __ldg(&be1[kk])
                + x0 * __ldg(&We1[kk])        + x1 * __ldg(&We1[256 + kk])
                + x2 * __ldg(&We1[512 + kk])  + x3 * __ldg(&We1[768 + kk])
                + x4 * __ldg(&We1[1024 + kk]) + x5 * __ldg(&We1[1280 + kk]);
        v[j] = fmaxf(t, 0.f);
    }
    u32 h, l;
    split2(v[0], v[1], h, l);
    *(u32*)(h1h + (size_t)r * 256 + c2) = h;
    *(u32*)(h1l + (size_t)r * 256 + c2) = l;
}

// ---------------- CSR build -------------------------------------------------
__global__ void count_deg(const int* __restrict__ ei, int E, int n,
                          int* degA, int* degL, int* degR) {
    int e = blockIdx.x * blockDim.x + threadIdx.x;
    if (e < E) {
        int s = ei[e], d = ei[E + e];
        atomicAdd(&degA[d], 1);
        atomicAdd(&degL[s], 1);
        atomicAdd(&degR[d], 1);
    } else if (e < E + n) {
        atomicAdd(&degA[e - E], 1);
    }
}

__global__ void scan3_kernel(const int* dA, int* rA, int* cA,
                             const int* dL, int* rL, int* cL,
                             const int* dR, int* rR, int* cR, int n) {
    const int* deg = blockIdx.x == 0 ? dA : (blockIdx.x == 1 ? dL : dR);
    int* rowoff    = blockIdx.x == 0 ? rA : (blockIdx.x == 1 ? rL : rR);
    int* cur       = blockIdx.x == 0 ? cA : (blockIdx.x == 1 ? cL : cR);
    __shared__ int sh[1024];
    __shared__ int carry;
    int tid = threadIdx.x;
    if (tid == 0) carry = 0;
    __syncthreads();
    for (int base = 0; base < n; base += 1024) {
        int i = base + tid;
        int v = (i < n) ? deg[i] : 0;
        sh[tid] = v;
        __syncthreads();
        for (int off = 1; off < 1024; off <<= 1) {
            int t = (tid >= off) ? sh[tid - off] : 0;
            __syncthreads();
            sh[tid] += t;
            __syncthreads();
        }
        int excl = sh[tid] - v + carry;
        if (i < n) { rowoff[i] = excl; cur[i] = excl; }
        __syncthreads();
        if (tid == 1023) carry += sh[1023];
        __syncthreads();
    }
    if (tid == 0) rowoff[n] = carry;
}

__global__ void fill_adj(const int* __restrict__ ei, int E, int n,
                         int* curA, int* adjA, int* curL, int* eidL,
                         int* curR, int* eidR) {
    int e = blockIdx.x * blockDim.x + threadIdx.x;
    if (e < E) {
        int s = ei[e], d = ei[E + e];
        int p = atomicAdd(&curA[d], 1); adjA[p] = s;
        p = atomicAdd(&curL[s], 1); eidL[p] = e;
        p = atomicAdd(&curR[d], 1); eidR[p] = e;
    } else if (e < E + n) {
        int node = e - E;
        int p = atomicAdd(&curA[node], 1); adjA[p] = node;
    }
}

// ---------------- mma.sync GEMM (2-stage cp.async, 2 CTAs/SM — R8 proven) ----
// C[M,N] = act(A @ W + bias); A given as split pair [M][K], W as split [N][K].
// 128x128 CTA tile, 8 warps of 32x64, BK=32 double-buffered, 3-term bf16 split.
// OUT_SPLIT==1: write (Ch, Cl) split bf16 instead of fp32 C (N must be full tiles).
#define APITCH 40
#define STAGE_BYTES 40960
template<int OUT_SPLIT>
__global__ __launch_bounds__(256, 2)
void mma_gemm(const bf16* __restrict__ Ah, const bf16* __restrict__ Al,
              const bf16* __restrict__ Bh, const bf16* __restrict__ Bl,
              const float* __restrict__ bias, float* __restrict__ C,
              bf16* __restrict__ Ch, bf16* __restrict__ Cl,
              int M, int N, int K, int Cld, int Nstore, int act) {
    extern __shared__ char dsm[];
    const u32 dbase = (smem_u32(dsm) + 127) & ~127u;
    const int tid = threadIdx.x, lane = tid & 31, wid = tid >> 5;
    const int mwarp = wid & 3, nwarp = wid >> 2;
    const int blockRow = blockIdx.y * 128, blockCol = blockIdx.x * 128;

    float acc[2][8][4];
#pragma unroll
    for (int m = 0; m < 2; m++)
#pragma unroll
        for (int n = 0; n < 8; n++)
#pragma unroll
            for (int j = 0; j < 4; j++) acc[m][n][j] = 0.f;

    const int nch = K >> 5;

    auto issue = [&](int c, int st) {
        int k0 = c << 5;
        u32 sb = dbase + st * STAGE_BYTES;
        // A hi/lo (rows may exceed M -> zfill)
#pragma unroll
        for (int l = 0; l < 4; l++) {
            int idx = tid + l * 256;
            int arr = idx >> 9, rem = idx & 511, row = rem >> 2, seg = rem & 3;
            int gr = blockRow + row;
            u32 sz = 16;
            if (gr >= M) { gr = 0; sz = 0; }
            const bf16* gsrc = (arr ? Al : Ah) + (size_t)gr * K + k0 + seg * 8;
            u32 sdst = sb + arr * 10240 + (row * APITCH + seg * 8) * 2;
            CP_ASYNC16Z(sdst, gsrc, sz);
        }
        // B hi/lo (always in-bounds)
#pragma unroll
        for (int l = 0; l < 4; l++) {
            int idx = tid + l * 256;
            int arr = idx >> 9, rem = idx & 511, row = rem >> 2, seg = rem & 3;
            const bf16* gsrc = (arr ? Bl : Bh) + (size_t)(blockCol + row) * K + k0 + seg * 8;
            u32 sdst = sb + (arr ? 30720 : 20480) + (row * APITCH + seg * 8) * 2;
            CP_ASYNC16(sdst, gsrc);
        }
        CP_COMMIT();
    };
    auto compute = [&](int st) {
        u32 sb = dbase + st * STAGE_BYTES;
        u32 Ah_ = sb, Al_ = sb + 10240, Bh_ = sb + 20480, Bl_ = sb + 30720;
        int arow = 32 * mwarp + (lane & 15);
        int acol = (lane >> 4) * 8;
        int brow = (lane & 7) + ((lane >> 4) << 3);
        int bcol = ((lane >> 3) & 1) * 8;
#pragma unroll
        for (int ks = 0; ks < 2; ks++) {
            int koff = ks * 16;
            u32 ah[2][4], al[2][4];
#pragma unroll
            for (int m = 0; m < 2; m++) {
                u32 ao = ((arow + m * 16) * APITCH + acol + koff) * 2;
                LDSM4(ah[m], Ah_ + ao);
                LDSM4(al[m], Al_ + ao);
            }
#pragma unroll
            for (int p = 0; p < 4; p++) {
                int n0 = 64 * nwarp + p * 16;
                u32 bo = ((n0 + brow) * APITCH + bcol + koff) * 2;
                u32 bh[4], bl[4];
                LDSM4(bh, Bh_ + bo);
                LDSM4(bl, Bl_ + bo);
#pragma unroll
                for (int m = 0; m < 2; m++) {
                    MMA16816(acc[m][2 * p],     ah[m], bh[0], bh[1]);
                    MMA16816(acc[m][2 * p],     ah[m], bl[0], bl[1]);
                    MMA16816(acc[m][2 * p],     al[m], bh[0], bh[1]);
                    MMA16816(acc[m][2 * p + 1], ah[m], bh[2], bh[3]);
                    MMA16816(acc[m][2 * p + 1], ah[m], bl[2], bl[3]);
                    MMA16816(acc[m][2 * p + 1], al[m], bh[2], bh[3]);
                }
            }
        }
    };

    issue(0, 0);
    int cur = 0;
    for (int c = 0; c < nch; c++) {
        if (c + 1 < nch) {
            issue(c + 1, cur ^ 1);
            CP_WAIT1();
        } else {
            CP_WAIT0();
        }
        __syncthreads();
        compute(cur);
        __syncthreads();
        cur ^= 1;
    }

    // ---- epilogue ----
    int g = lane >> 2, t = lane & 3;
#pragma unroll
    for (int m = 0; m < 2; m++) {
        int row0 = blockRow + 32 * mwarp + m * 16 + g;
#pragma unroll
        for (int nt = 0; nt < 8; nt++) {
            int col0 = blockCol + 64 * nwarp + nt * 8 + t * 2;
#pragma unroll
            for (int half = 0; half < 2; half++) {
                int r = row0 + half * 8;
                if (r >= M) continue;
                float v0 = acc[m][nt][half * 2 + 0];
                float v1 = acc[m][nt][half * 2 + 1];
                if (bias) { v0 += bias[col0]; v1 += bias[col0 + 1]; }
                if (act) { v0 = fmaxf(v0, 0.f); v1 = fmaxf(v1, 0.f); }
                if constexpr (OUT_SPLIT) {
                    u32 h, l;
                    split2(v0, v1, h, l);
                    *(u32*)(Ch + (size_t)r * Cld + col0) = h;
                    *(u32*)(Cl + (size_t)r * Cld + col0) = l;
                } else {
                    if (col0 < Nstore)     C[(size_t)r * Cld + col0] = v0;
                    if (col0 + 1 < Nstore) C[(size_t)r * Cld + col0 + 1] = v1;
                }
            }
        }
    }
}

// ---------------- GAT attention scalars -------------------------------------
__global__ void sd_kernel(const float* __restrict__ xl, const float* __restrict__ asr,
                          const float* __restrict__ adt, float* __restrict__ s,
                          float* __restrict__ d, int n, int H, int C) {
    int warp = (blockIdx.x * blockDim.x + threadIdx.x) >> 5;
    int lane = threadIdx.x & 31;
    if (warp >= n * H) return;
    int node = warp / H, h = warp - node * H;
    const float* row = xl + (size_t)node * H * C + (size_t)h * C;
    float ss = 0.f, dd = 0.f;
    for (int c = lane; c < C; c += 32) {
        float v = row[c];
        ss += v * asr[h * C + c];
        dd += v * adt[h * C + c];
    }
#pragma unroll
    for (int o = 16; o; o >>= 1) {
        ss += __shfl_down_sync(~0u, ss, o);
        dd += __shfl_down_sync(~0u, dd, o);
    }
    if (!lane) { s[warp] = ss; d[warp] = dd; }
}

// ---------------- GAT aggregation (CSR, atomic-free, split bf16 output) -----
template<int H, int C>
__launch_bounds__(256)
__global__ void gat_agg(const int* __restrict__ row, const int* __restrict__ adj,
                        const float* __restrict__ s, const float* __restrict__ dvec,
                        const float* __restrict__ xl, const float* __restrict__ bias,
                        bf16* __restrict__ outh, bf16* __restrict__ outl,
                        int ldout, int doElu) {
    constexpr int HC = H * C;
    constexpr int CAP = 512;
    constexpr int PT = (HC + 255) / 256;
    __shared__ float al[CAP * H];
    __shared__ int asrc[CAP];
    __shared__ float mh[8], zinv[8];

    int n = blockIdx.x, tid = threadIdx.x, w = tid >> 5, lane = tid & 31;
    int start = row[n], deg = row[n + 1] - start;

    if (w < H) {
        float dh = dvec[n * H + w];
        float m = -FLT_MAX;
        for (int i = lane; i < deg; i += 32) {
            float a = s[adj[start + i] * H + w] + dh;
            a = a > 0.f ? a : 0.2f * a;
            m = fmaxf(m, a);
        }
#pragma unroll
        for (int o = 16; o; o >>= 1) m = fmaxf(m, __shfl_xor_sync(~0u, m, o));
        float z = 0.f;
        for (int i = lane; i < deg; i += 32) {
            float a = s[adj[start + i] * H + w] + dh;
            a = a > 0.f ? a : 0.2f * a;
            z += expf(a - m);
        }
#pragma unroll
        for (int o = 16; o; o >>= 1) z += __shfl_xor_sync(~0u, z, o);
        if (lane == 0) { mh[w] = m; zinv[w] = 1.f / (z + 1e-16f); }
    }
    __syncthreads();

    float acc[PT];
#pragma unroll
    for (int p = 0; p < PT; p++) {
        int c = tid + p * 256;
        acc[p] = (c < HC) ? bias[c] : 0.f;
    }

    for (int base = 0; base < deg; base += CAP) {
        int cnt = min(CAP, deg - base);
        __syncthreads();
        for (int i = tid; i < cnt; i += 256) asrc[i] = adj[start + base + i];
        __syncthreads();
        for (int i = tid; i < cnt * H; i += 256) {
            int e = i / H, h = i - e * H;
            float a = s[asrc[e] * H + h] + dvec[n * H + h];
            a = a > 0.f ? a : 0.2f * a;
            al[e * H + h] = expf(a - mh[h]) * zinv[h];
        }
        __syncthreads();
#pragma unroll
        for (int p = 0; p < PT; p++) {
            int c = tid + p * 256;
            if (c < HC) {
                int h = c / C;
                float a = acc[p];
                for (int i = 0; i < cnt; i++)
                    a += al[i * H + h] * xl[(size_t)asrc[i] * HC + c];
                acc[p] = a;
            }
        }
    }

#pragma unroll
    for (int p = 0; p < PT; p++) {
        int c = tid + p * 256;
        if (c < HC) {
            float v = acc[p];
            if (doElu) v = v > 0.f ? v : expm1f(v);
            bf16 h, l;
            split1(v, h, l);
            outh[(size_t)n * ldout + c] = h;
            outl[(size_t)n * ldout + c] = l;
        }
    }
}

// ---------------- merged scatter-mean (L and R in one launch) ----------------
__launch_bounds__(256)
__global__ void mean_gather2(const int* __restrict__ rowL, const int* __restrict__ eidL,
                             const int* __restrict__ rowR, const int* __restrict__ eidR,
                             const float* __restrict__ xp2, bf16* __restrict__ finh,
                             bf16* __restrict__ finl) {
    __shared__ int eids[512];
    int n = blockIdx.x, tid = threadIdx.x;
#pragma unroll
    for (int side = 0; side < 2; side++) {
        const int* row = side ? rowR : rowL;
        const int* eid = side ? eidR : eidL;
        int off = side ? 1024 : 512;
        int start = row[n], deg = row[n + 1] - start;
        float a0 = 0.f, a1 = 0.f;
        for (int base = 0; base < deg; base += 512) {
            int cnt = min(512, deg - base);
            __syncthreads();
            for (int i = tid; i < cnt; i += 256) eids[i] = eid[start + base + i];
            __syncthreads();
            for (int i = 0; i < cnt; i++) {
                const float* r = xp2 + (size_t)eids[i] * 512;
                a0 += r[tid];
                a1 += r[tid + 256];
            }
        }
        float inv = 1.f / fmaxf((float)deg, 1.f);
        a0 *= inv; a1 *= inv;
        bf16 h, l;
        split1(a0, h, l);
        finh[(size_t)n * 1536 + off + tid] = h;
        finl[(size_t)n * 1536 + off + tid] = l;
        split1(a1, h, l);
        finh[(size_t)n * 1536 + off + tid + 256] = h;
        finl[(size_t)n * 1536 + off + tid + 256] = l;
        __syncthreads();
    }
}

// ---------------- synapse max-pool ------------------------------------------
__global__ void synapse_max(const float* __restrict__ syn, const int* __restrict__ sidx,
                            int* __restrict__ xpi, int P) {
    int idx = blockIdx.x * blockDim.x + threadIdx.x;
    if (idx >= P * 6) return;
    int p = idx / 6, f = idx - p * 6;
    atomicMax(&xpi[(size_t)sidx[p] * 6 + f], mono_enc(syn[(size_t)p * 6 + f]));
}

// ---------------- host ------------------------------------------------------
static inline int g1(long long total) { return (int)((total + 255) / 256); }
#define GEMM_DSM (2 * STAGE_BYTES + 128)

extern "C" void kernel_launch(void* const* d_in, const int* in_sizes, int n_in,
                              void* d_out, int out_size) {
    const int*   ei   = (const int*)d_in[0];
    const float* syn  = (const float*)d_in[2];
    const int*   sidx = (const int*)d_in[3];
    const float* x_p  = (const float*)d_in[5];
    const float* W1   = (const float*)d_in[6];
    const float* as1  = (const float*)d_in[7];
    const float* ad1  = (const float*)d_in[8];
    const float* b1   = (const float*)d_in[9];
    const float* W2   = (const float*)d_in[10];
    const float* as2  = (const float*)d_in[11];
    const float* ad2  = (const float*)d_in[12];
    const float* b2   = (const float*)d_in[13];
    const float* We1  = (const float*)d_in[14];
    const float* be1  = (const float*)d_in[15];
    const float* We2  = (const float*)d_in[16];
    const float* be2  = (const float*)d_in[17];
    const float* Wc1  = (const float*)d_in[18];
    const float* bc1  = (const float*)d_in[19];
    const float* Wc2  = (const float*)d_in[20];
    const float* bc2  = (const float*)d_in[21];

    const int E = in_sizes[0] / 2;
    const int P = in_sizes[2] / 6;
    const int N = in_sizes[5] / 128;
    const int NCLS = in_sizes[20] / 512;
    float* out = (float*)d_out;

    float *bufA, *s, *d, *xp2;
    int *xpi, *degA, *degL, *degR, *rowA, *rowL, *rowR, *curA, *curL, *curR,
        *adjA, *eidL, *eidR;
    bf16 *xph, *xpl, *h1h, *h1l, *x1h, *x1l, *finh, *finl, *hch, *hcl;
    bf16 *w1h, *w1l, *w2h, *w2l, *we2h, *we2l, *wc1h, *wc1l, *wc2h, *wc2l;
    cudaGetSymbolAddress((void**)&bufA, g_bufA);
    cudaGetSymbolAddress((void**)&s,    g_s);
    cudaGetSymbolAddress((void**)&d,    g_d);
    cudaGetSymbolAddress((void**)&xpi,  g_xpi);
    cudaGetSymbolAddress((void**)&xp2,  g_xp2);
    cudaGetSymbolAddress((void**)&degA, g_degA);
    cudaGetSymbolAddress((void**)&degL, g_degL);
    cudaGetSymbolAddress((void**)&degR, g_degR);
    cudaGetSymbolAddress((void**)&rowA, g_rowA);
    cudaGetSymbolAddress((void**)&rowL, g_rowL);
    cudaGetSymbolAddress((void**)&rowR, g_rowR);
    cudaGetSymbolAddress((void**)&curA, g_curA);
    cudaGetSymbolAddress((void**)&curL, g_curL);
    cudaGetSymbolAddress((void**)&curR, g_curR);
    cudaGetSymbolAddress((void**)&adjA, g_adjA);
    cudaGetSymbolAddress((void**)&eidL, g_eidL);
    cudaGetSymbolAddress((void**)&eidR, g_eidR);
    cudaGetSymbolAddress((void**)&xph, g_xph);  cudaGetSymbolAddress((void**)&xpl, g_xpl);
    cudaGetSymbolAddress((void**)&h1h, g_h1h);  cudaGetSymbolAddress((void**)&h1l, g_h1l);
    cudaGetSymbolAddress((void**)&x1h, g_x1h);  cudaGetSymbolAddress((void**)&x1l, g_x1l);
    cudaGetSymbolAddress((void**)&finh, g_finh); cudaGetSymbolAddress((void**)&finl, g_finl);
    cudaGetSymbolAddress((void**)&hch, g_hch);  cudaGetSymbolAddress((void**)&hcl, g_hcl);
    cudaGetSymbolAddress((void**)&w1h, g_w1h);  cudaGetSymbolAddress((void**)&w1l, g_w1l);
    cudaGetSymbolAddress((void**)&w2h, g_w2h);  cudaGetSymbolAddress((void**)&w2l, g_w2l);
    cudaGetSymbolAddress((void**)&we2h, g_we2h); cudaGetSymbolAddress((void**)&we2l, g_we2l);
    cudaGetSymbolAddress((void**)&wc1h, g_wc1h); cudaGetSymbolAddress((void**)&wc1l, g_wc1l);
    cudaGetSymbolAddress((void**)&wc2h, g_wc2h); cudaGetSymbolAddress((void**)&wc2l, g_wc2l);

    cudaFuncSetAttribute(mma_gemm<0>, cudaFuncAttributeMaxDynamicSharedMemorySize, GEMM_DSM);
    cudaFuncSetAttribute(mma_gemm<1>, cudaFuncAttributeMaxDynamicSharedMemorySize, GEMM_DSM);

    // ===== synapse branch first (big GEMM early for ncu capture) =====
    fill_int<<<g1((long long)E * 6), 256>>>(xpi, 0x80800000, E * 6);
    synapse_max<<<g1((long long)P * 6), 256>>>(syn, sidx, xpi, P);
    mlp1_split<<<g1((long long)E * 128), 256>>>(xpi, We1, be1, h1h, h1l, E);
    prep_w<<<g1(512LL * 256), 256>>>(We2, we2h, we2l, 256, 512, 512);
    split_f32<<<g1((long long)N * 64), 256>>>(x_p, xph, xpl, (long long)N * 128);
    {
        dim3 g(4, (E + 127) / 128);
        mma_gemm<0><<<g, 256, GEMM_DSM>>>(h1h, h1l, we2h, we2l, be2, xp2,
                                          nullptr, nullptr, E, 512, 256, 512, 512, 0);
    }

    // ===== remaining weight prep =====
    prep_w<<<g1(512LL * 128), 256>>>(W1, w1h, w1l, 128, 512, 512);
    prep_w<<<g1(512LL * 512), 256>>>(W2, w2h, w2l, 512, 512, 512);
    prep_w<<<g1(512LL * 1536), 256>>>(Wc1, wc1h, wc1l, 1536, 512, 512);
    prep_w<<<g1(256LL * 512), 256>>>(Wc2, wc2h, wc2l, 512, 256, NCLS);

    // ===== CSR build =====
    fill_int<<<g1(N), 256>>>(degA, 0, N);
    fill_int<<<g1(N), 256>>>(degL, 0, N);
    fill_int<<<g1(N), 256>>>(degR, 0, N);
    count_deg<<<g1(E + N), 256>>>(ei, E, N, degA, degL, degR);
    scan3_kernel<<<3, 1024>>>(degA, rowA, curA, degL, rowL, curL, degR, rowR, curR, N);
    fill_adj<<<g1(E + N), 256>>>(ei, E, N, curA, adjA, curL, eidL, curR, eidR);

    // ===== GAT layer 1 =====
    {
        dim3 g(4, (N + 127) / 128);
        mma_gemm<0><<<g, 256, GEMM_DSM>>>(xph, xpl, w1h, w1l, nullptr, bufA,
                                          nullptr, nullptr, N, 512, 128, 512, 512, 0);
    }
    sd_kernel<<<g1((long long)N * 8 * 32), 256>>>(bufA, as1, ad1, s, d, N, 8, 64);
    gat_agg<8, 64><<<N, 256>>>(rowA, adjA, s, d, bufA, b1, x1h, x1l, 512, 1);

    // ===== GAT layer 2 =====
    {
        dim3 g(4, (N + 127) / 128);
        mma_gemm<0><<<g, 256, GEMM_DSM>>>(x1h, x1l, w2h, w2l, nullptr, bufA,
                                          nullptr, nullptr, N, 512, 512, 512, 512, 0);
    }
    sd_kernel<<<g1((long long)N * 32), 256>>>(bufA, as2, ad2, s, d, N, 1, 512);
    gat_agg<1, 512><<<N, 256>>>(rowA, adjA, s, d, bufA, b2, finh, finl, 1536, 0);

    // ===== scatter means into fin[:,512:1536] =====
    mean_gather2<<<N, 256>>>(rowL, eidL, rowR, eidR, xp2, finh, finl);

    // ===== classifier =====
    {
        dim3 g(4, (N + 127) / 128);
        mma_gemm<1><<<g, 256, GEMM_DSM>>>(finh, finl, wc1h, wc1l, bc1, nullptr,
                                          hch, hcl, N, 512, 1536, 512, 512, 1);
    }
    {
        dim3 g(2, (N + 127) / 128);
        mma_gemm<0><<<g, 256, GEMM_DSM>>>(hch, hcl, wc2h, wc2l, bc2, out,
                                          nullptr, nullptr, N, 256, 512, NCLS, NCLS, 0);
    }
}

// round 15
// speedup vs baseline: 1.4746x; 1.2881x over previous
#include <cuda_runtime.h>
#include <cuda_fp16.h>
#include <math.h>
#include <float.h>

#define NMAX 20000
#define EMAX 200000

typedef unsigned long long ull;
typedef unsigned int u32;
typedef __half hlf;

// ---------------- scratch (device globals; no allocation allowed) ----------
__device__ float g_bufA[NMAX * 512];          // xl (fp32, GEMM out for GAT layers)
__device__ float g_s[NMAX * 8];
__device__ float g_d[NMAX * 8];
__device__ int   g_xpi[EMAX * 6];
__device__ hlf   g_xp2[EMAX * 512];           // synapse MLP out (fp16)
__device__ int g_degA[NMAX], g_degL[NMAX], g_degR[NMAX];
__device__ int g_rowA[NMAX + 1], g_rowL[NMAX + 1], g_rowR[NMAX + 1];
__device__ int g_curA[NMAX], g_curL[NMAX], g_curR[NMAX];
__device__ int g_adjA[EMAX + NMAX];
__device__ int g_eidL[EMAX], g_eidR[EMAX];
// activations
__device__ hlf g_xph[NMAX * 128],  g_xpl[NMAX * 128];   // x_param pair (TERMS=3)
__device__ hlf g_h1[EMAX * 256];                        // h1 single (TERMS=2)
__device__ hlf g_x1h[NMAX * 512],  g_x1l[NMAX * 512];   // x1 pair (TERMS=3)
__device__ hlf g_fin[NMAX * 1536];                      // fin single (TERMS=2)
__device__ hlf g_hc[NMAX * 512];                        // hc single (TERMS=2)
// fp16 split weights, transposed to [N][K]
__device__ hlf g_w1h[512 * 128],  g_w1l[512 * 128];
__device__ hlf g_w2h[512 * 512],  g_w2l[512 * 512];
__device__ hlf g_we2h[512 * 256], g_we2l[512 * 256];
__device__ hlf g_wc1h[512 * 1536], g_wc1l[512 * 1536];
__device__ hlf g_wc2h[256 * 512], g_wc2l[256 * 512];

// ---------------- PTX helpers (baseline ISA only) ----------------------------
__device__ __forceinline__ u32 smem_u32(const void* p) {
    u32 a;
    asm("{ .reg .u64 t; cvta.to.shared.u64 t, %1; cvt.u32.u64 %0, t; }" : "=r"(a) : "l"(p));
    return a;
}
#define LDSM4(r, addr) \
    asm volatile("ldmatrix.sync.aligned.m8n8.x4.shared.b16 {%0,%1,%2,%3}, [%4];" \
        : "=r"((r)[0]), "=r"((r)[1]), "=r"((r)[2]), "=r"((r)[3]) : "r"(addr))
#define MMA16816(c, a, b0, b1) \
    asm volatile("mma.sync.aligned.m16n8k16.row.col.f32.f16.f16.f32 " \
        "{%0,%1,%2,%3}, {%4,%5,%6,%7}, {%8,%9}, {%0,%1,%2,%3};" \
        : "+f"((c)[0]), "+f"((c)[1]), "+f"((c)[2]), "+f"((c)[3]) \
        : "r"((a)[0]), "r"((a)[1]), "r"((a)[2]), "r"((a)[3]), "r"(b0), "r"(b1))
#define CP_ASYNC16(s, g) \
    asm volatile("cp.async.ca.shared.global [%0], [%1], 16;" :: "r"(s), "l"(g))
#define CP_ASYNC16Z(s, g, sz) \
    asm volatile("cp.async.ca.shared.global [%0], [%1], 16, %2;" :: "r"(s), "l"(g), "r"(sz))
#define CP_COMMIT() asm volatile("cp.async.commit_group;" ::: "memory")
#define CP_WAIT0()  asm volatile("cp.async.wait_group 0;" ::: "memory")
#define CP_WAIT1()  asm volatile("cp.async.wait_group 1;" ::: "memory")

__device__ __forceinline__ u32 pack_h2(float x, float y) {
    __half2 h = __floats2half2_rn(x, y);
    return *reinterpret_cast<u32*>(&h);
}
__device__ __forceinline__ void split2h(float x, float y, u32& hi, u32& lo) {
    __half2 h = __floats2half2_rn(x, y);
    float hx = __low2float(h), hy = __high2float(h);
    __half2 l = __floats2half2_rn(x - hx, y - hy);
    hi = *reinterpret_cast<u32*>(&h);
    lo = *reinterpret_cast<u32*>(&l);
}
__device__ __forceinline__ void split1h(float v, hlf& h, hlf& l) {
    h = __float2half_rn(v);
    l = __float2half_rn(v - __half2float(h));
}

// ---------------- monotonic float<->int for atomicMax ----------------------
__device__ __forceinline__ int mono_enc(float f) {
    int i = __float_as_int(f);
    return i >= 0 ? i : (i ^ 0x7FFFFFFF);
}
__device__ __forceinline__ float mono_dec(int i) {
    int j = i >= 0 ? i : (i ^ 0x7FFFFFFF);
    return __int_as_float(j);
}

// ---------------- tiny utility kernels -------------------------------------
__global__ void fill_int(int* p, int v, int n) {
    int i = blockIdx.x * blockDim.x + threadIdx.x;
    if (i < n) p[i] = v;
}

// W[K,Nsrc] -> Wh/Wl[N][K] fp16 split (pad cols Nsrc..N-1 with 0)
__global__ void prep_w(const float* __restrict__ W, hlf* __restrict__ Wh,
                       hlf* __restrict__ Wl, int K, int N, int Nsrc) {
    long long i = (long long)blockIdx.x * 256 + threadIdx.x;
    if (i >= (long long)N * K) return;
    int n = (int)(i / K), k = (int)(i - (long long)n * K);
    float v = (n < Nsrc) ? W[(size_t)k * Nsrc + n] : 0.f;
    hlf h, l;
    split1h(v, h, l);
    Wh[i] = h; Wl[i] = l;
}

// X fp32 -> (Xh, Xl) fp16 split, 2 elements per thread
__global__ void split_f32(const float* __restrict__ X, hlf* __restrict__ Xh,
                          hlf* __restrict__ Xl, long long n) {
    long long i = ((long long)blockIdx.x * 256 + threadIdx.x) * 2;
    if (i >= n) return;
    u32 h, l;
    split2h(X[i], X[i + 1], h, l);
    *(u32*)(Xh + i) = h;
    *(u32*)(Xl + i) = l;
}

// h1 = relu(decode(xpi) @ We1 + be1), single fp16. 2 cols/thread.
__global__ void mlp1_fp16(const int* __restrict__ xpi, const float* __restrict__ We1,
                          const float* __restrict__ be1, hlf* __restrict__ h1, int E) {
    long long idx = (long long)blockIdx.x * 256 + threadIdx.x;
    if (idx >= (long long)E * 128) return;
    int r = (int)(idx >> 7), c2 = ((int)idx & 127) << 1;
    float x0 = mono_dec(__ldg(&xpi[r * 6 + 0]));
    float x1 = mono_dec(__ldg(&xpi[r * 6 + 1]));
    float x2 = mono_dec(__ldg(&xpi[r * 6 + 2]));
    float x3 = mono_dec(__ldg(&xpi[r * 6 + 3]));
    float x4 = mono_dec(__ldg(&xpi[r * 6 + 4]));
    float x5 = mono_dec(__ldg(&xpi[r * 6 + 5]));
    float v[2];
#pragma unroll
    for (int j = 0; j < 2; j++) {
        int kk = c2 + j;
        float t = __ldg(&be1[kk])
                + x0 * __ldg(&We1[kk])        + x1 * __ldg(&We1[256 + kk])
                + x2 * __ldg(&We1[512 + kk])  + x3 * __ldg(&We1[768 + kk])
                + x4 * __ldg(&We1[1024 + kk]) + x5 * __ldg(&We1[1280 + kk]);
        v[j] = fmaxf(t, 0.f);
    }
    *(u32*)(h1 + (size_t)r * 256 + c2) = pack_h2(v[0], v[1]);
}

// ---------------- CSR build -------------------------------------------------
__global__ void count_deg(const int* __restrict__ ei, int E, int n,
                          int* degA, int* degL, int* degR) {
    int e = blockIdx.x * blockDim.x + threadIdx.x;
    if (e < E) {
        int s = ei[e], d = ei[E + e];
        atomicAdd(&degA[d], 1);
        atomicAdd(&degL[s], 1);
        atomicAdd(&degR[d], 1);
    } else if (e < E + n) {
        atomicAdd(&degA[e - E], 1);
    }
}

__global__ void scan3_kernel(const int* dA, int* rA, int* cA,
                             const int* dL, int* rL, int* cL,
                             const int* dR, int* rR, int* cR, int n) {
    const int* deg = blockIdx.x == 0 ? dA : (blockIdx.x == 1 ? dL : dR);
    int* rowoff    = blockIdx.x == 0 ? rA : (blockIdx.x == 1 ? rL : rR);
    int* cur       = blockIdx.x == 0 ? cA : (blockIdx.x == 1 ? cL : cR);
    __shared__ int sh[1024];
    __shared__ int carry;
    int tid = threadIdx.x;
    if (tid == 0) carry = 0;
    __syncthreads();
    for (int base = 0; base < n; base += 1024) {
        int i = base + tid;
        int v = (i < n) ? deg[i] : 0;
        sh[tid] = v;
        __syncthreads();
        for (int off = 1; off < 1024; off <<= 1) {
            int t = (tid >= off) ? sh[tid - off] : 0;
            __syncthreads();
            sh[tid] += t;
            __syncthreads();
        }
        int excl = sh[tid] - v + carry;
        if (i < n) { rowoff[i] = excl; cur[i] = excl; }
        __syncthreads();
        if (tid == 1023) carry += sh[1023];
        __syncthreads();
    }
    if (tid == 0) rowoff[n] = carry;
}

__global__ void fill_adj(const int* __restrict__ ei, int E, int n,
                         int* curA, int* adjA, int* curL, int* eidL,
                         int* curR, int* eidR) {
    int e = blockIdx.x * blockDim.x + threadIdx.x;
    if (e < E) {
        int s = ei[e], d = ei[E + e];
        int p = atomicAdd(&curA[d], 1); adjA[p] = s;
        p = atomicAdd(&curL[s], 1); eidL[p] = e;
        p = atomicAdd(&curR[d], 1); eidR[p] = e;
    } else if (e < E + n) {
        int node = e - E;
        int p = atomicAdd(&curA[node], 1); adjA[p] = node;
    }
}

// ---------------- mma.sync GEMM (fp16, 2- or 3-term, 2-stage, 2 CTAs/SM) ----
// C[M,N] = act(A @ W + bias); W as fp16 split pair [N][K].
// TERMS=3: A is fp16 pair (Ah,Al); D = ah*bh + ah*bl + al*bh (fp32-accurate).
// TERMS=2: A is single fp16;      D = a*bh + a*bl (a-rounding ~2^-11).
// OUT=0: fp32 C (bias/store guarded by Nstore). OUT=1: packed fp16 Ch (full tiles).
#define APITCH 40
template<int TERMS, int OUT>
__global__ __launch_bounds__(256, 2)
void mma_gemm(const hlf* __restrict__ Ah, const hlf* __restrict__ Al,
              const hlf* __restrict__ Bh, const hlf* __restrict__ Bl,
              const float* __restrict__ bias, float* __restrict__ C,
              hlf* __restrict__ Ch,
              int M, int N, int K, int Cld, int Nstore, int act) {
    constexpr int STB = (TERMS == 3) ? 40960 : 30720;
    constexpr u32 AHOFF = 0;
    constexpr u32 ALOFF = 10240;                       // TERMS=3 only
    constexpr u32 BHOFF = (TERMS == 3) ? 20480 : 10240;
    constexpr u32 BLOFF = BHOFF + 10240;
    extern __shared__ char dsm[];
    const u32 dbase = (smem_u32(dsm) + 127) & ~127u;
    const int tid = threadIdx.x, lane = tid & 31, wid = tid >> 5;
    const int mwarp = wid & 3, nwarp = wid >> 2;
    const int blockRow = blockIdx.y * 128, blockCol = blockIdx.x * 128;

    float acc[2][8][4];
#pragma unroll
    for (int m = 0; m < 2; m++)
#pragma unroll
        for (int n = 0; n < 8; n++)
#pragma unroll
            for (int j = 0; j < 4; j++) acc[m][n][j] = 0.f;

    const int nch = K >> 5;

    auto issue = [&](int c, int st) {
        int k0 = c << 5;
        u32 sb = dbase + st * STB;
        if constexpr (TERMS == 3) {
#pragma unroll
            for (int l = 0; l < 4; l++) {
                int idx = tid + l * 256;
                int arr = idx >> 9, rem = idx & 511, row = rem >> 2, seg = rem & 3;
                int gr = blockRow + row;
                u32 sz = 16;
                if (gr >= M) { gr = 0; sz = 0; }
                const hlf* gsrc = (arr ? Al : Ah) + (size_t)gr * K + k0 + seg * 8;
                CP_ASYNC16Z(sb + (arr ? ALOFF : AHOFF) + (row * APITCH + seg * 8) * 2, gsrc, sz);
            }
        } else {
#pragma unroll
            for (int l = 0; l < 2; l++) {
                int idx = tid + l * 256;
                int row = idx >> 2, seg = idx & 3;
                int gr = blockRow + row;
                u32 sz = 16;
                if (gr >= M) { gr = 0; sz = 0; }
                const hlf* gsrc = Ah + (size_t)gr * K + k0 + seg * 8;
                CP_ASYNC16Z(sb + (row * APITCH + seg * 8) * 2, gsrc, sz);
            }
        }
#pragma unroll
        for (int l = 0; l < 4; l++) {
            int idx = tid + l * 256;
            int arr = idx >> 9, rem = idx & 511, row = rem >> 2, seg = rem & 3;
            const hlf* gsrc = (arr ? Bl : Bh) + (size_t)(blockCol + row) * K + k0 + seg * 8;
            CP_ASYNC16(sb + (arr ? BLOFF : BHOFF) + (row * APITCH + seg * 8) * 2, gsrc);
        }
        CP_COMMIT();
    };
    auto compute = [&](int st) {
        u32 sb = dbase + st * STB;
        int arow = 32 * mwarp + (lane & 15);
        int acol = (lane >> 4) * 8;
        int brow = (lane & 7) + ((lane >> 4) << 3);
        int bcol = ((lane >> 3) & 1) * 8;
#pragma unroll
        for (int ks = 0; ks < 2; ks++) {
            int koff = ks * 16;
            u32 ah[2][4], al[2][4];
#pragma unroll
            for (int m = 0; m < 2; m++) {
                u32 ao = ((arow + m * 16) * APITCH + acol + koff) * 2;
                LDSM4(ah[m], sb + AHOFF + ao);
                if constexpr (TERMS == 3) LDSM4(al[m], sb + ALOFF + ao);
            }
#pragma unroll
            for (int p = 0; p < 4; p++) {
                int n0 = 64 * nwarp + p * 16;
                u32 bo = ((n0 + brow) * APITCH + bcol + koff) * 2;
                u32 bh[4], bl[4];
                LDSM4(bh, sb + BHOFF + bo);
                LDSM4(bl, sb + BLOFF + bo);
#pragma unroll
                for (int m = 0; m < 2; m++) {
                    MMA16816(acc[m][2 * p],     ah[m], bh[0], bh[1]);
                    MMA16816(acc[m][2 * p],     ah[m], bl[0], bl[1]);
                    MMA16816(acc[m][2 * p + 1], ah[m], bh[2], bh[3]);
                    MMA16816(acc[m][2 * p + 1], ah[m], bl[2], bl[3]);
                    if constexpr (TERMS == 3) {
                        MMA16816(acc[m][2 * p],     al[m], bh[0], bh[1]);
                        MMA16816(acc[m][2 * p + 1], al[m], bh[2], bh[3]);
                    }
                }
            }
        }
    };

    issue(0, 0);
    int cur = 0;
    for (int c = 0; c < nch; c++) {
        if (c + 1 < nch) {
            issue(c + 1, cur ^ 1);
            CP_WAIT1();
        } else {
            CP_WAIT0();
        }
        __syncthreads();
        compute(cur);
        __syncthreads();
        cur ^= 1;
    }

    // ---- epilogue ----
    int g = lane >> 2, t = lane & 3;
#pragma unroll
    for (int m = 0; m < 2; m++) {
        int row0 = blockRow + 32 * mwarp + m * 16 + g;
#pragma unroll
        for (int nt = 0; nt < 8; nt++) {
            int col0 = blockCol + 64 * nwarp + nt * 8 + t * 2;
#pragma unroll
            for (int half = 0; half < 2; half++) {
                int r = row0 + half * 8;
                if (r >= M) continue;
                float v0 = acc[m][nt][half * 2 + 0];
                float v1 = acc[m][nt][half * 2 + 1];
                if (bias) {
                    if (col0 < Nstore)     v0 += bias[col0];
                    if (col0 + 1 < Nstore) v1 += bias[col0 + 1];
                }
                if (act) { v0 = fmaxf(v0, 0.f); v1 = fmaxf(v1, 0.f); }
                if constexpr (OUT == 1) {
                    *(u32*)(Ch + (size_t)r * Cld + col0) = pack_h2(v0, v1);
                } else {
                    if (col0 < Nstore)     C[(size_t)r * Cld + col0] = v0;
                    if (col0 + 1 < Nstore) C[(size_t)r * Cld + col0 + 1] = v1;
                }
            }
        }
    }
}

// ---------------- GAT attention scalars -------------------------------------
__global__ void sd_kernel(const float* __restrict__ xl, const float* __restrict__ asr,
                          const float* __restrict__ adt, float* __restrict__ s,
                          float* __restrict__ d, int n, int H, int C) {
    int warp = (blockIdx.x * blockDim.x + threadIdx.x) >> 5;
    int lane = threadIdx.x & 31;
    if (warp >= n * H) return;
    int node = warp / H, h = warp - node * H;
    const float* row = xl + (size_t)node * H * C + (size_t)h * C;
    float ss = 0.f, dd = 0.f;
    for (int c = lane; c < C; c += 32) {
        float v = row[c];
        ss += v * asr[h * C + c];
        dd += v * adt[h * C + c];
    }
#pragma unroll
    for (int o = 16; o; o >>= 1) {
        ss += __shfl_down_sync(~0u, ss, o);
        dd += __shfl_down_sync(~0u, dd, o);
    }
    if (!lane) { s[warp] = ss; d[warp] = dd; }
}

// ---------------- GAT aggregation (CSR, atomic-free) ------------------------
// PAIR=1: write fp16 hi/lo pair. PAIR=0: write single fp16.
template<int H, int C, int PAIR>
__launch_bounds__(256)
__global__ void gat_agg(const int* __restrict__ row, const int* __restrict__ adj,
                        const float* __restrict__ s, const float* __restrict__ dvec,
                        const float* __restrict__ xl, const float* __restrict__ bias,
                        hlf* __restrict__ outh, hlf* __restrict__ outl,
                        int ldout, int doElu) {
    constexpr int HC = H * C;
    constexpr int CAP = 512;
    constexpr int PT = (HC + 255) / 256;
    __shared__ float al[CAP * H];
    __shared__ int asrc[CAP];
    __shared__ float mh[8], zinv[8];

    int n = blockIdx.x, tid = threadIdx.x, w = tid >> 5, lane = tid & 31;
    int start = row[n], deg = row[n + 1] - start;

    if (w < H) {
        float dh = dvec[n * H + w];
        float m = -FLT_MAX;
        for (int i = lane; i < deg; i += 32) {
            float a = s[adj[start + i] * H + w] + dh;
            a = a > 0.f ? a : 0.2f * a;
            m = fmaxf(m, a);
        }
#pragma unroll
        for (int o = 16; o; o >>= 1) m = fmaxf(m, __shfl_xor_sync(~0u, m, o));
        float z = 0.f;
        for (int i = lane; i < deg; i += 32) {
            float a = s[adj[start + i] * H + w] + dh;
            a = a > 0.f ? a : 0.2f * a;
            z += expf(a - m);
        }
#pragma unroll
        for (int o = 16; o; o >>= 1) z += __shfl_xor_sync(~0u, z, o);
        if (lane == 0) { mh[w] = m; zinv[w] = 1.f / (z + 1e-16f); }
    }
    __syncthreads();

    float acc[PT];
#pragma unroll
    for (int p = 0; p < PT; p++) {
        int c = tid + p * 256;
        acc[p] = (c < HC) ? bias[c] : 0.f;
    }

    for (int base = 0; base < deg; base += CAP) {
        int cnt = min(CAP, deg - base);
        __syncthreads();
        for (int i = tid; i < cnt; i += 256) asrc[i] = adj[start + base + i];
        __syncthreads();
        for (int i = tid; i < cnt * H; i += 256) {
            int e = i / H, h = i - e * H;
            float a = s[asrc[e] * H + h] + dvec[n * H + h];
            a = a > 0.f ? a : 0.2f * a;
            al[e * H + h] = expf(a - mh[h]) * zinv[h];
        }
        __syncthreads();
#pragma unroll
        for (int p = 0; p < PT; p++) {
            int c = tid + p * 256;
            if (c < HC) {
                int h = c / C;
                float a = acc[p];
                for (int i = 0; i < cnt; i++)
                    a += al[i * H + h] * xl[(size_t)asrc[i] * HC + c];
                acc[p] = a;
            }
        }
    }

#pragma unroll
    for (int p = 0; p < PT; p++) {
        int c = tid + p * 256;
        if (c < HC) {
            float v = acc[p];
            if (doElu) v = v > 0.f ? v : expm1f(v);
            if constexpr (PAIR) {
                hlf h, l;
                split1h(v, h, l);
                outh[(size_t)n * ldout + c] = h;
                outl[(size_t)n * ldout + c] = l;
            } else {
                outh[(size_t)n * ldout + c] = __float2half_rn(v);
            }
        }
    }
}

// ---------------- merged scatter-mean (L and R; fp16 in, fp16 out) ----------
// Each thread owns ONE half2 (2 columns): 256 threads x 2 = 512 cols per row.
__launch_bounds__(256)
__global__ void mean_gather2(const int* __restrict__ rowL, const int* __restrict__ eidL,
                             const int* __restrict__ rowR, const int* __restrict__ eidR,
                             const hlf* __restrict__ xp2, hlf* __restrict__ fin) {
    __shared__ int eids[512];
    int n = blockIdx.x, tid = threadIdx.x;
#pragma unroll
    for (int side = 0; side < 2; side++) {
        const int* row = side ? rowR : rowL;
        const int* eid = side ? eidR : eidL;
        int off = side ? 1024 : 512;
        int start = row[n], deg = row[n + 1] - start;
        float a0 = 0.f, a1 = 0.f;
        for (int base = 0; base < deg; base += 512) {
            int cnt = min(512, deg - base);
            __syncthreads();
            for (int i = tid; i < cnt; i += 256) eids[i] = eid[start + base + i];
            __syncthreads();
            for (int i = 0; i < cnt; i++) {
                const __half2* r = (const __half2*)(xp2 + (size_t)eids[i] * 512);
                float2 f = __half22float2(r[tid]);
                a0 += f.x; a1 += f.y;
            }
        }
        float inv = 1.f / fmaxf((float)deg, 1.f);
        *(u32*)(fin + (size_t)n * 1536 + off + tid * 2) = pack_h2(a0 * inv, a1 * inv);
        __syncthreads();
    }
}

// ---------------- synapse max-pool ------------------------------------------
__global__ void synapse_max(const float* __restrict__ syn, const int* __restrict__ sidx,
                            int* __restrict__ xpi, int P) {
    int idx = blockIdx.x * blockDim.x + threadIdx.x;
    if (idx >= P * 6) return;
    int p = idx / 6, f = idx - p * 6;
    atomicMax(&xpi[(size_t)sidx[p] * 6 + f], mono_enc(syn[(size_t)p * 6 + f]));
}

// ---------------- host ------------------------------------------------------
static inline int g1(long long total) { return (int)((total + 255) / 256); }
#define DSM3 (2 * 40960 + 128)
#define DSM2 (2 * 30720 + 128)

extern "C" void kernel_launch(void* const* d_in, const int* in_sizes, int n_in,
                              void* d_out, int out_size) {
    const int*   ei   = (const int*)d_in[0];
    const float* syn  = (const float*)d_in[2];
    const int*   sidx = (const int*)d_in[3];
    const float* x_p  = (const float*)d_in[5];
    const float* W1   = (const float*)d_in[6];
    const float* as1  = (const float*)d_in[7];
    const float* ad1  = (const float*)d_in[8];
    const float* b1   = (const float*)d_in[9];
    const float* W2   = (const float*)d_in[10];
    const float* as2  = (const float*)d_in[11];
    const float* ad2  = (const float*)d_in[12];
    const float* b2   = (const float*)d_in[13];
    const float* We1  = (const float*)d_in[14];
    const float* be1  = (const float*)d_in[15];
    const float* We2  = (const float*)d_in[16];
    const float* be2  = (const float*)d_in[17];
    const float* Wc1  = (const float*)d_in[18];
    const float* bc1  = (const float*)d_in[19];
    const float* Wc2  = (const float*)d_in[20];
    const float* bc2  = (const float*)d_in[21];

    const int E = in_sizes[0] / 2;
    const int P = in_sizes[2] / 6;
    const int N = in_sizes[5] / 128;
    const int NCLS = in_sizes[20] / 512;
    float* out = (float*)d_out;

    float *bufA, *s, *d;
    int *xpi, *degA, *degL, *degR, *rowA, *rowL, *rowR, *curA, *curL, *curR,
        *adjA, *eidL, *eidR;
    hlf *xp2, *xph, *xpl, *h1, *x1h, *x1l, *fin, *hc;
    hlf *w1h, *w1l, *w2h, *w2l, *we2h, *we2l, *wc1h, *wc1l, *wc2h, *wc2l;
    cudaGetSymbolAddress((void**)&bufA, g_bufA);
    cudaGetSymbolAddress((void**)&s,    g_s);
    cudaGetSymbolAddress((void**)&d,    g_d);
    cudaGetSymbolAddress((void**)&xpi,  g_xpi);
    cudaGetSymbolAddress((void**)&xp2,  g_xp2);
    cudaGetSymbolAddress((void**)&degA, g_degA);
    cudaGetSymbolAddress((void**)&degL, g_degL);
    cudaGetSymbolAddress((void**)&degR, g_degR);
    cudaGetSymbolAddress((void**)&rowA, g_rowA);
    cudaGetSymbolAddress((void**)&rowL, g_rowL);
    cudaGetSymbolAddress((void**)&rowR, g_rowR);
    cudaGetSymbolAddress((void**)&curA, g_curA);
    cudaGetSymbolAddress((void**)&curL, g_curL);
    cudaGetSymbolAddress((void**)&curR, g_curR);
    cudaGetSymbolAddress((void**)&adjA, g_adjA);
    cudaGetSymbolAddress((void**)&eidL, g_eidL);
    cudaGetSymbolAddress((void**)&eidR, g_eidR);
    cudaGetSymbolAddress((void**)&xph, g_xph);  cudaGetSymbolAddress((void**)&xpl, g_xpl);
    cudaGetSymbolAddress((void**)&h1,  g_h1);
    cudaGetSymbolAddress((void**)&x1h, g_x1h);  cudaGetSymbolAddress((void**)&x1l, g_x1l);
    cudaGetSymbolAddress((void**)&fin, g_fin);
    cudaGetSymbolAddress((void**)&hc,  g_hc);
    cudaGetSymbolAddress((void**)&w1h, g_w1h);  cudaGetSymbolAddress((void**)&w1l, g_w1l);
    cudaGetSymbolAddress((void**)&w2h, g_w2h);  cudaGetSymbolAddress((void**)&w2l, g_w2l);
    cudaGetSymbolAddress((void**)&we2h, g_we2h); cudaGetSymbolAddress((void**)&we2l, g_we2l);
    cudaGetSymbolAddress((void**)&wc1h, g_wc1h); cudaGetSymbolAddress((void**)&wc1l, g_wc1l);
    cudaGetSymbolAddress((void**)&wc2h, g_wc2h); cudaGetSymbolAddress((void**)&wc2l, g_wc2l);

    cudaFuncSetAttribute(mma_gemm<3, 0>, cudaFuncAttributeMaxDynamicSharedMemorySize, DSM3);
    cudaFuncSetAttribute(mma_gemm<2, 0>, cudaFuncAttributeMaxDynamicSharedMemorySize, DSM2);
    cudaFuncSetAttribute(mma_gemm<2, 1>, cudaFuncAttributeMaxDynamicSharedMemorySize, DSM2);

    // ===== synapse branch first =====
    fill_int<<<g1((long long)E * 6), 256>>>(xpi, 0x80800000, E * 6);
    synapse_max<<<g1((long long)P * 6), 256>>>(syn, sidx, xpi, P);
    mlp1_fp16<<<g1((long long)E * 128), 256>>>(xpi, We1, be1, h1, E);
    prep_w<<<g1(512LL * 256), 256>>>(We2, we2h, we2l, 256, 512, 512);
    split_f32<<<g1((long long)N * 64), 256>>>(x_p, xph, xpl, (long long)N * 128);
    {
        dim3 g(4, (E + 127) / 128);
        mma_gemm<2, 1><<<g, 256, DSM2>>>(h1, nullptr, we2h, we2l, be2, nullptr,
                                         xp2, E, 512, 256, 512, 512, 0);
    }

    // ===== remaining weight prep =====
    prep_w<<<g1(512LL * 128), 256>>>(W1, w1h, w1l, 128, 512, 512);
    prep_w<<<g1(512LL * 512), 256>>>(W2, w2h, w2l, 512, 512, 512);
    prep_w<<<g1(512LL * 1536), 256>>>(Wc1, wc1h, wc1l, 1536, 512, 512);
    prep_w<<<g1(256LL * 512), 256>>>(Wc2, wc2h, wc2l, 512, 256, NCLS);

    // ===== CSR build =====
    fill_int<<<g1(N), 256>>>(degA, 0, N);
    fill_int<<<g1(N), 256>>>(degL, 0, N);
    fill_int<<<g1(N), 256>>>(degR, 0, N);
    count_deg<<<g1(E + N), 256>>>(ei, E, N, degA, degL, degR);
    scan3_kernel<<<3, 1024>>>(degA, rowA, curA, degL, rowL, curL, degR, rowR, curR, N);
    fill_adj<<<g1(E + N), 256>>>(ei, E, N, curA, adjA, curL, eidL, curR, eidR);

    // ===== GAT layer 1 =====
    {
        dim3 g(4, (N + 127) / 128);
        mma_gemm<3, 0><<<g, 256, DSM3>>>(xph, xpl, w1h, w1l, nullptr, bufA,
                                         nullptr, N, 512, 128, 512, 512, 0);
    }
    sd_kernel<<<g1((long long)N * 8 * 32), 256>>>(bufA, as1, ad1, s, d, N, 8, 64);
    gat_agg<8, 64, 1><<<N, 256>>>(rowA, adjA, s, d, bufA, b1, x1h, x1l, 512, 1);

    // ===== GAT layer 2 =====
    {
        dim3 g(4, (N + 127) / 128);
        mma_gemm<3, 0><<<g, 256, DSM3>>>(x1h, x1l, w2h, w2l, nullptr, bufA,
                                         nullptr, N, 512, 512, 512, 512, 0);
    }
    sd_kernel<<<g1((long long)N * 32), 256>>>(bufA, as2, ad2, s, d, N, 1, 512);
    gat_agg<1, 512, 0><<<N, 256>>>(rowA, adjA, s, d, bufA, b2, fin, nullptr, 1536, 0);

    // ===== scatter means into fin[:,512:1536] =====
    mean_gather2<<<N, 256>>>(rowL, eidL, rowR, eidR, xp2, fin);

    // ===== classifier =====
    {
        dim3 g(4, (N + 127) / 128);
        mma_gemm<2, 1><<<g, 256, DSM2>>>(fin, nullptr, wc1h, wc1l, bc1, nullptr,
                                         hc, N, 512, 1536, 512, 512, 1);
    }
    {
        dim3 g(2, (N + 127) / 128);
        mma_gemm<2, 0><<<g, 256, DSM2>>>(hc, nullptr, wc2h, wc2l, bc2, out,
                                         nullptr, N, 256, 512, NCLS, NCLS, 0);
    }
}

// round 17
// speedup vs baseline: 1.7191x; 1.1658x over previous
#include <cuda_runtime.h>
#include <cuda_fp16.h>
#include <math.h>
#include <float.h>

#define NMAX 20000
#define EMAX 200000

typedef unsigned long long ull;
typedef unsigned int u32;
typedef __half hlf;

// ---------------- scratch (device globals; no allocation allowed) ----------
__device__ float g_bufA[NMAX * 512];          // xl (fp32, GEMM out for GAT layers)
__device__ float g_s[NMAX * 8];
__device__ float g_d[NMAX * 8];
__device__ int   g_xpi[EMAX * 6];
__device__ hlf   g_xp2[EMAX * 512];           // synapse MLP out (fp16)
__device__ int g_degA[NMAX], g_degL[NMAX], g_degR[NMAX];
__device__ int g_rowA[NMAX + 1], g_rowL[NMAX + 1], g_rowR[NMAX + 1];
__device__ int g_curA[NMAX], g_curL[NMAX], g_curR[NMAX];
__device__ int g_adjA[EMAX + NMAX];
__device__ int g_eidL[EMAX], g_eidR[EMAX];
// activations
__device__ hlf g_xph[NMAX * 128],  g_xpl[NMAX * 128];   // x_param pair (TERMS=3)
__device__ hlf g_h1[EMAX * 256];                        // h1 single
__device__ hlf g_x1h[NMAX * 512],  g_x1l[NMAX * 512];   // x1 pair (TERMS=3)
__device__ hlf g_fin[NMAX * 1536];                      // fin single
__device__ hlf g_hc[NMAX * 512];                        // hc single
// fp16 split weights, transposed to [N][K] (lo plane unused for 1-term layers)
__device__ hlf g_w1h[512 * 128],  g_w1l[512 * 128];
__device__ hlf g_w2h[512 * 512],  g_w2l[512 * 512];
__device__ hlf g_we2h[512 * 256], g_we2l[512 * 256];
__device__ hlf g_wc1h[512 * 1536], g_wc1l[512 * 1536];
__device__ hlf g_wc2h[256 * 512], g_wc2l[256 * 512];

// ---------------- PTX helpers (baseline ISA only) ----------------------------
__device__ __forceinline__ u32 smem_u32(const void* p) {
    u32 a;
    asm("{ .reg .u64 t; cvta.to.shared.u64 t, %1; cvt.u32.u64 %0, t; }" : "=r"(a) : "l"(p));
    return a;
}
#define LDSM4(r, addr) \
    asm volatile("ldmatrix.sync.aligned.m8n8.x4.shared.b16 {%0,%1,%2,%3}, [%4];" \
        : "=r"((r)[0]), "=r"((r)[1]), "=r"((r)[2]), "=r"((r)[3]) : "r"(addr))
#define MMA16816(c, a, b0, b1) \
    asm volatile("mma.sync.aligned.m16n8k16.row.col.f32.f16.f16.f32 " \
        "{%0,%1,%2,%3}, {%4,%5,%6,%7}, {%8,%9}, {%0,%1,%2,%3};" \
        : "+f"((c)[0]), "+f"((c)[1]), "+f"((c)[2]), "+f"((c)[3]) \
        : "r"((a)[0]), "r"((a)[1]), "r"((a)[2]), "r"((a)[3]), "r"(b0), "r"(b1))
#define CP_ASYNC16(s, g) \
    asm volatile("cp.async.ca.shared.global [%0], [%1], 16;" :: "r"(s), "l"(g))
#define CP_ASYNC16Z(s, g, sz) \
    asm volatile("cp.async.ca.shared.global [%0], [%1], 16, %2;" :: "r"(s), "l"(g), "r"(sz))
#define CP_COMMIT() asm volatile("cp.async.commit_group;" ::: "memory")
#define CP_WAIT0()  asm volatile("cp.async.wait_group 0;" ::: "memory")
#define CP_WAIT1()  asm volatile("cp.async.wait_group 1;" ::: "memory")

__device__ __forceinline__ u32 pack_h2(float x, float y) {
    __half2 h = __floats2half2_rn(x, y);
    return *reinterpret_cast<u32*>(&h);
}
__device__ __forceinline__ void split2h(float x, float y, u32& hi, u32& lo) {
    __half2 h = __floats2half2_rn(x, y);
    float hx = __low2float(h), hy = __high2float(h);
    __half2 l = __floats2half2_rn(x - hx, y - hy);
    hi = *reinterpret_cast<u32*>(&h);
    lo = *reinterpret_cast<u32*>(&l);
}
__device__ __forceinline__ void split1h(float v, hlf& h, hlf& l) {
    h = __float2half_rn(v);
    l = __float2half_rn(v - __half2float(h));
}

// ---------------- monotonic float<->int for atomicMax ----------------------
__device__ __forceinline__ int mono_enc(float f) {
    int i = __float_as_int(f);
    return i >= 0 ? i : (i ^ 0x7FFFFFFF);
}
__device__ __forceinline__ float mono_dec(int i) {
    int j = i >= 0 ? i : (i ^ 0x7FFFFFFF);
    return __int_as_float(j);
}

// ---------------- tiny utility kernels -------------------------------------
__global__ void fill_int(int* p, int v, int n) {
    int i = blockIdx.x * blockDim.x + threadIdx.x;
    if (i < n) p[i] = v;
}

// W[K,Nsrc] -> Wh/Wl[N][K] fp16 split (pad cols Nsrc..N-1 with 0)
__global__ void prep_w(const float* __restrict__ W, hlf* __restrict__ Wh,
                       hlf* __restrict__ Wl, int K, int N, int Nsrc) {
    long long i = (long long)blockIdx.x * 256 + threadIdx.x;
    if (i >= (long long)N * K) return;
    int n = (int)(i / K), k = (int)(i - (long long)n * K);
    float v = (n < Nsrc) ? W[(size_t)k * Nsrc + n] : 0.f;
    hlf h, l;
    split1h(v, h, l);
    Wh[i] = h;
    if (Wl) Wl[i] = l;
}

// X fp32 -> (Xh, Xl) fp16 split, 2 elements per thread
__global__ void split_f32(const float* __restrict__ X, hlf* __restrict__ Xh,
                          hlf* __restrict__ Xl, long long n) {
    long long i = ((long long)blockIdx.x * 256 + threadIdx.x) * 2;
    if (i >= n) return;
    u32 h, l;
    split2h(X[i], X[i + 1], h, l);
    *(u32*)(Xh + i) = h;
    *(u32*)(Xl + i) = l;
}

// h1 = relu(decode(xpi) @ We1 + be1), single fp16. 2 cols/thread.
__global__ void mlp1_fp16(const int* __restrict__ xpi, const float* __restrict__ We1,
                          const float* __restrict__ be1, hlf* __restrict__ h1, int E) {
    long long idx = (long long)blockIdx.x * 256 + threadIdx.x;
    if (idx >= (long long)E * 128) return;
    int r = (int)(idx >> 7), c2 = ((int)idx & 127) << 1;
    float x0 = mono_dec(__ldg(&xpi[r * 6 + 0]));
    float x1 = mono_dec(__ldg(&xpi[r * 6 + 1]));
    float x2 = mono_dec(__ldg(&xpi[r * 6 + 2]));
    float x3 = mono_dec(__ldg(&xpi[r * 6 + 3]));
    float x4 = mono_dec(__ldg(&xpi[r * 6 + 4]));
    float x5 = mono_dec(__ldg(&xpi[r * 6 + 5]));
    float v[2];
#pragma unroll
    for (int j = 0; j < 2; j++) {
        int kk = c2 + j;
        float t = __ldg(&be1[kk])
                + x0 * __ldg(&We1[kk])        + x1 * __ldg(&We1[256 + kk])
                + x2 * __ldg(&We1[512 + kk])  + x3 * __ldg(&We1[768 + kk])
                + x4 * __ldg(&We1[1024 + kk]) + x5 * __ldg(&We1[1280 + kk]);
        v[j] = fmaxf(t, 0.f);
    }
    *(u32*)(h1 + (size_t)r * 256 + c2) = pack_h2(v[0], v[1]);
}

// ---------------- CSR build -------------------------------------------------
__global__ void count_deg(const int* __restrict__ ei, int E, int n,
                          int* degA, int* degL, int* degR) {
    int e = blockIdx.x * blockDim.x + threadIdx.x;
    if (e < E) {
        int s = ei[e], d = ei[E + e];
        atomicAdd(&degA[d], 1);
        atomicAdd(&degL[s], 1);
        atomicAdd(&degR[d], 1);
    } else if (e < E + n) {
        atomicAdd(&degA[e - E], 1);
    }
}

__global__ void scan3_kernel(const int* dA, int* rA, int* cA,
                             const int* dL, int* rL, int* cL,
                             const int* dR, int* rR, int* cR, int n) {
    const int* deg = blockIdx.x == 0 ? dA : (blockIdx.x == 1 ? dL : dR);
    int* rowoff    = blockIdx.x == 0 ? rA : (blockIdx.x == 1 ? rL : rR);
    int* cur       = blockIdx.x == 0 ? cA : (blockIdx.x == 1 ? cL : cR);
    __shared__ int sh[1024];
    __shared__ int carry;
    int tid = threadIdx.x;
    if (tid == 0) carry = 0;
    __syncthreads();
    for (int base = 0; base < n; base += 1024) {
        int i = base + tid;
        int v = (i < n) ? deg[i] : 0;
        sh[tid] = v;
        __syncthreads();
        for (int off = 1; off < 1024; off <<= 1) {
            int t = (tid >= off) ? sh[tid - off] : 0;
            __syncthreads();
            sh[tid] += t;
            __syncthreads();
        }
        int excl = sh[tid] - v + carry;
        if (i < n) { rowoff[i] = excl; cur[i] = excl; }
        __syncthreads();
        if (tid == 1023) carry += sh[1023];
        __syncthreads();
    }
    if (tid == 0) rowoff[n] = carry;
}

__global__ void fill_adj(const int* __restrict__ ei, int E, int n,
                         int* curA, int* adjA, int* curL, int* eidL,
                         int* curR, int* eidR) {
    int e = blockIdx.x * blockDim.x + threadIdx.x;
    if (e < E) {
        int s = ei[e], d = ei[E + e];
        int p = atomicAdd(&curA[d], 1); adjA[p] = s;
        p = atomicAdd(&curL[s], 1); eidL[p] = e;
        p = atomicAdd(&curR[d], 1); eidR[p] = e;
    } else if (e < E + n) {
        int node = e - E;
        int p = atomicAdd(&curA[node], 1); adjA[p] = node;
    }
}

// ---------------- mma.sync GEMM (fp16, 1/2/3-term, 2-stage, 2 CTAs/SM) ------
// C[M,N] = act(A @ W + bias).
// TERMS=3: A pair, W pair; D = ah*bh + ah*bl + al*bh (fp32-grade).
// TERMS=2: A single, W pair; a-rounding only (~2^-11).
// TERMS=1: A single, W single; plain fp16 (a+b rounding, ~2^-11 each).
// OUT=0: fp32 C (guarded by Nstore). OUT=1: packed fp16 Ch (full tiles).
#define APITCH 40
template<int TERMS, int OUT>
__global__ __launch_bounds__(256, 2)
void mma_gemm(const hlf* __restrict__ Ah, const hlf* __restrict__ Al,
              const hlf* __restrict__ Bh, const hlf* __restrict__ Bl,
              const float* __restrict__ bias, float* __restrict__ C,
              hlf* __restrict__ Ch,
              int M, int N, int K, int Cld, int Nstore, int act) {
    constexpr int STB = (TERMS == 3) ? 40960 : (TERMS == 2 ? 30720 : 20480);
    constexpr u32 AHOFF = 0;
    constexpr u32 ALOFF = 10240;                       // TERMS=3 only
    constexpr u32 BHOFF = (TERMS == 3) ? 20480 : 10240;
    constexpr u32 BLOFF = BHOFF + 10240;               // TERMS>=2 only
    extern __shared__ char dsm[];
    const u32 dbase = (smem_u32(dsm) + 127) & ~127u;
    const int tid = threadIdx.x, lane = tid & 31, wid = tid >> 5;
    const int mwarp = wid & 3, nwarp = wid >> 2;
    const int blockRow = blockIdx.y * 128, blockCol = blockIdx.x * 128;

    float acc[2][8][4];
#pragma unroll
    for (int m = 0; m < 2; m++)
#pragma unroll
        for (int n = 0; n < 8; n++)
#pragma unroll
            for (int j = 0; j < 4; j++) acc[m][n][j] = 0.f;

    const int nch = K >> 5;

    auto issue = [&](int c, int st) {
        int k0 = c << 5;
        u32 sb = dbase + st * STB;
        if constexpr (TERMS == 3) {
#pragma unroll
            for (int l = 0; l < 4; l++) {
                int idx = tid + l * 256;
                int arr = idx >> 9, rem = idx & 511, row = rem >> 2, seg = rem & 3;
                int gr = blockRow + row;
                u32 sz = 16;
                if (gr >= M) { gr = 0; sz = 0; }
                const hlf* gsrc = (arr ? Al : Ah) + (size_t)gr * K + k0 + seg * 8;
                CP_ASYNC16Z(sb + (arr ? ALOFF : AHOFF) + (row * APITCH + seg * 8) * 2, gsrc, sz);
            }
        } else {
#pragma unroll
            for (int l = 0; l < 2; l++) {
                int idx = tid + l * 256;
                int row = idx >> 2, seg = idx & 3;
                int gr = blockRow + row;
                u32 sz = 16;
                if (gr >= M) { gr = 0; sz = 0; }
                const hlf* gsrc = Ah + (size_t)gr * K + k0 + seg * 8;
                CP_ASYNC16Z(sb + (row * APITCH + seg * 8) * 2, gsrc, sz);
            }
        }
        if constexpr (TERMS >= 2) {
#pragma unroll
            for (int l = 0; l < 4; l++) {
                int idx = tid + l * 256;
                int arr = idx >> 9, rem = idx & 511, row = rem >> 2, seg = rem & 3;
                const hlf* gsrc = (arr ? Bl : Bh) + (size_t)(blockCol + row) * K + k0 + seg * 8;
                CP_ASYNC16(sb + (arr ? BLOFF : BHOFF) + (row * APITCH + seg * 8) * 2, gsrc);
            }
        } else {
#pragma unroll
            for (int l = 0; l < 2; l++) {
                int idx = tid + l * 256;
                int row = idx >> 2, seg = idx & 3;
                const hlf* gsrc = Bh + (size_t)(blockCol + row) * K + k0 + seg * 8;
                CP_ASYNC16(sb + BHOFF + (row * APITCH + seg * 8) * 2, gsrc);
            }
        }
        CP_COMMIT();
    };
    auto compute = [&](int st) {
        u32 sb = dbase + st * STB;
        int arow = 32 * mwarp + (lane & 15);
        int acol = (lane >> 4) * 8;
        int brow = (lane & 7) + ((lane >> 4) << 3);
        int bcol = ((lane >> 3) & 1) * 8;
#pragma unroll
        for (int ks = 0; ks < 2; ks++) {
            int koff = ks * 16;
            u32 ah[2][4], al[2][4];
#pragma unroll
            for (int m = 0; m < 2; m++) {
                u32 ao = ((arow + m * 16) * APITCH + acol + koff) * 2;
                LDSM4(ah[m], sb + AHOFF + ao);
                if constexpr (TERMS == 3) LDSM4(al[m], sb + ALOFF + ao);
            }
#pragma unroll
            for (int p = 0; p < 4; p++) {
                int n0 = 64 * nwarp + p * 16;
                u32 bo = ((n0 + brow) * APITCH + bcol + koff) * 2;
                u32 bh[4], bl[4];
                LDSM4(bh, sb + BHOFF + bo);
                if constexpr (TERMS >= 2) LDSM4(bl, sb + BLOFF + bo);
#pragma unroll
                for (int m = 0; m < 2; m++) {
                    MMA16816(acc[m][2 * p],     ah[m], bh[0], bh[1]);
                    MMA16816(acc[m][2 * p + 1], ah[m], bh[2], bh[3]);
                    if constexpr (TERMS >= 2) {
                        MMA16816(acc[m][2 * p],     ah[m], bl[0], bl[1]);
                        MMA16816(acc[m][2 * p + 1], ah[m], bl[2], bl[3]);
                    }
                    if constexpr (TERMS == 3) {
                        MMA16816(acc[m][2 * p],     al[m], bh[0], bh[1]);
                        MMA16816(acc[m][2 * p + 1], al[m], bh[2], bh[3]);
                    }
                }
            }
        }
    };

    issue(0, 0);
    int cur = 0;
    for (int c = 0; c < nch; c++) {
        if (c + 1 < nch) {
            issue(c + 1, cur ^ 1);
            CP_WAIT1();
        } else {
            CP_WAIT0();
        }
        __syncthreads();
        compute(cur);
        __syncthreads();
        cur ^= 1;
    }

    // ---- epilogue ----
    int g = lane >> 2, t = lane & 3;
#pragma unroll
    for (int m = 0; m < 2; m++) {
        int row0 = blockRow + 32 * mwarp + m * 16 + g;
#pragma unroll
        for (int nt = 0; nt < 8; nt++) {
            int col0 = blockCol + 64 * nwarp + nt * 8 + t * 2;
#pragma unroll
            for (int half = 0; half < 2; half++) {
                int r = row0 + half * 8;
                if (r >= M) continue;
                float v0 = acc[m][nt][half * 2 + 0];
                float v1 = acc[m][nt][half * 2 + 1];
                if (bias) {
                    if (col0 < Nstore)     v0 += bias[col0];
                    if (col0 + 1 < Nstore) v1 += bias[col0 + 1];
                }
                if (act) { v0 = fmaxf(v0, 0.f); v1 = fmaxf(v1, 0.f); }
                if constexpr (OUT == 1) {
                    *(u32*)(Ch + (size_t)r * Cld + col0) = pack_h2(v0, v1);
                } else {
                    if (col0 < Nstore)     C[(size_t)r * Cld + col0] = v0;
                    if (col0 + 1 < Nstore) C[(size_t)r * Cld + col0 + 1] = v1;
                }
            }
        }
    }
}

// ---------------- GAT attention scalars -------------------------------------
__global__ void sd_kernel(const float* __restrict__ xl, const float* __restrict__ asr,
                          const float* __restrict__ adt, float* __restrict__ s,
                          float* __restrict__ d, int n, int H, int C) {
    int warp = (blockIdx.x * blockDim.x + threadIdx.x) >> 5;
    int lane = threadIdx.x & 31;
    if (warp >= n * H) return;
    int node = warp / H, h = warp - node * H;
    const float* row = xl + (size_t)node * H * C + (size_t)h * C;
    float ss = 0.f, dd = 0.f;
    for (int c = lane; c < C; c += 32) {
        float v = row[c];
        ss += v * asr[h * C + c];
        dd += v * adt[h * C + c];
    }
#pragma unroll
    for (int o = 16; o; o >>= 1) {
        ss += __shfl_down_sync(~0u, ss, o);
        dd += __shfl_down_sync(~0u, dd, o);
    }
    if (!lane) { s[warp] = ss; d[warp] = dd; }
}

// ---------------- GAT aggregation (CSR, atomic-free) ------------------------
// PAIR=1: write fp16 hi/lo pair. PAIR=0: write single fp16.
template<int H, int C, int PAIR>
__launch_bounds__(256)
__global__ void gat_agg(const int* __restrict__ row, const int* __restrict__ adj,
                        const float* __restrict__ s, const float* __restrict__ dvec,
                        const float* __restrict__ xl, const float* __restrict__ bias,
                        hlf* __restrict__ outh, hlf* __restrict__ outl,
                        int ldout, int doElu) {
    constexpr int HC = H * C;
    constexpr int CAP = 512;
    constexpr int PT = (HC + 255) / 256;
    __shared__ float al[CAP * H];
    __shared__ int asrc[CAP];
    __shared__ float mh[8], zinv[8];

    int n = blockIdx.x, tid = threadIdx.x, w = tid >> 5, lane = tid & 31;
    int start = row[n], deg = row[n + 1] - start;

    if (w < H) {
        float dh = dvec[n * H + w];
        float m = -FLT_MAX;
        for (int i = lane; i < deg; i += 32) {
            float a = s[adj[start + i] * H + w] + dh;
            a = a > 0.f ? a : 0.2f * a;
            m = fmaxf(m, a);
        }
#pragma unroll
        for (int o = 16; o; o >>= 1) m = fmaxf(m, __shfl_xor_sync(~0u, m, o));
        float z = 0.f;
        for (int i = lane; i < deg; i += 32) {
            float a = s[adj[start + i] * H + w] + dh;
            a = a > 0.f ? a : 0.2f * a;
            z += expf(a - m);
        }
#pragma unroll
        for (int o = 16; o; o >>= 1) z += __shfl_xor_sync(~0u, z, o);
        if (lane == 0) { mh[w] = m; zinv[w] = 1.f / (z + 1e-16f); }
    }
    __syncthreads();

    float acc[PT];
#pragma unroll
    for (int p = 0; p < PT; p++) {
        int c = tid + p * 256;
        acc[p] = (c < HC) ? bias[c] : 0.f;
    }

    for (int base = 0; base < deg; base += CAP) {
        int cnt = min(CAP, deg - base);
        __syncthreads();
        for (int i = tid; i < cnt; i += 256) asrc[i] = adj[start + base + i];
        __syncthreads();
        for (int i = tid; i < cnt * H; i += 256) {
            int e = i / H, h = i - e * H;
            float a = s[asrc[e] * H + h] + dvec[n * H + h];
            a = a > 0.f ? a : 0.2f * a;
            al[e * H + h] = expf(a - mh[h]) * zinv[h];
        }
        __syncthreads();
#pragma unroll
        for (int p = 0; p < PT; p++) {
            int c = tid + p * 256;
            if (c < HC) {
                int h = c / C;
                float a = acc[p];
                for (int i = 0; i < cnt; i++)
                    a += al[i * H + h] * xl[(size_t)asrc[i] * HC + c];
                acc[p] = a;
            }
        }
    }

#pragma unroll
    for (int p = 0; p < PT; p++) {
        int c = tid + p * 256;
        if (c < HC) {
            float v = acc[p];
            if (doElu) v = v > 0.f ? v : expm1f(v);
            if constexpr (PAIR) {
                hlf h, l;
                split1h(v, h, l);
                outh[(size_t)n * ldout + c] = h;
                outl[(size_t)n * ldout + c] = l;
            } else {
                outh[(size_t)n * ldout + c] = __float2half_rn(v);
            }
        }
    }
}

// ---------------- merged scatter-mean (L and R; fp16 in, fp16 out) ----------
// Each thread owns ONE half2 (2 columns): 256 threads x 2 = 512 cols per row.
__launch_bounds__(256)
__global__ void mean_gather2(const int* __restrict__ rowL, const int* __restrict__ eidL,
                             const int* __restrict__ rowR, const int* __restrict__ eidR,
                             const hlf* __restrict__ xp2, hlf* __restrict__ fin) {
    __shared__ int eids[512];
    int n = blockIdx.x, tid = threadIdx.x;
#pragma unroll
    for (int side = 0; side < 2; side++) {
        const int* row = side ? rowR : rowL;
        const int* eid = side ? eidR : eidL;
        int off = side ? 1024 : 512;
        int start = row[n], deg = row[n + 1] - start;
        float a0 = 0.f, a1 = 0.f;
        for (int base = 0; base < deg; base += 512) {
            int cnt = min(512, deg - base);
            __syncthreads();
            for (int i = tid; i < cnt; i += 256) eids[i] = eid[start + base + i];
            __syncthreads();
            for (int i = 0; i < cnt; i++) {
                const __half2* r = (const __half2*)(xp2 + (size_t)eids[i] * 512);
                float2 f = __half22float2(r[tid]);
                a0 += f.x; a1 += f.y;
            }
        }
        float inv = 1.f / fmaxf((float)deg, 1.f);
        *(u32*)(fin + (size_t)n * 1536 + off + tid * 2) = pack_h2(a0 * inv, a1 * inv);
        __syncthreads();
    }
}

// ---------------- synapse max-pool ------------------------------------------
__global__ void synapse_max(const float* __restrict__ syn, const int* __restrict__ sidx,
                            int* __restrict__ xpi, int P) {
    int idx = blockIdx.x * blockDim.x + threadIdx.x;
    if (idx >= P * 6) return;
    int p = idx / 6, f = idx - p * 6;
    atomicMax(&xpi[(size_t)sidx[p] * 6 + f], mono_enc(syn[(size_t)p * 6 + f]));
}

// ---------------- host ------------------------------------------------------
static inline int g1(long long total) { return (int)((total + 255) / 256); }
#define DSM3 (2 * 40960 + 128)
#define DSM1 (2 * 20480 + 128)

extern "C" void kernel_launch(void* const* d_in, const int* in_sizes, int n_in,
                              void* d_out, int out_size) {
    const int*   ei   = (const int*)d_in[0];
    const float* syn  = (const float*)d_in[2];
    const int*   sidx = (const int*)d_in[3];
    const float* x_p  = (const float*)d_in[5];
    const float* W1   = (const float*)d_in[6];
    const float* as1  = (const float*)d_in[7];
    const float* ad1  = (const float*)d_in[8];
    const float* b1   = (const float*)d_in[9];
    const float* W2   = (const float*)d_in[10];
    const float* as2  = (const float*)d_in[11];
    const float* ad2  = (const float*)d_in[12];
    const float* b2   = (const float*)d_in[13];
    const float* We1  = (const float*)d_in[14];
    const float* be1  = (const float*)d_in[15];
    const float* We2  = (const float*)d_in[16];
    const float* be2  = (const float*)d_in[17];
    const float* Wc1  = (const float*)d_in[18];
    const float* bc1  = (const float*)d_in[19];
    const float* Wc2  = (const float*)d_in[20];
    const float* bc2  = (const float*)d_in[21];

    const int E = in_sizes[0] / 2;
    const int P = in_sizes[2] / 6;
    const int N = in_sizes[5] / 128;
    const int NCLS = in_sizes[20] / 512;
    float* out = (float*)d_out;

    float *bufA, *s, *d;
    int *xpi, *degA, *degL, *degR, *rowA, *rowL, *rowR, *curA, *curL, *curR,
        *adjA, *eidL, *eidR;
    hlf *xp2, *xph, *xpl, *h1, *x1h, *x1l, *fin, *hc;
    hlf *w1h, *w1l, *w2h, *w2l, *we2h, *wc1h, *wc2h;
    cudaGetSymbolAddress((void**)&bufA, g_bufA);
    cudaGetSymbolAddress((void**)&s,    g_s);
    cudaGetSymbolAddress((void**)&d,    g_d);
    cudaGetSymbolAddress((void**)&xpi,  g_xpi);
    cudaGetSymbolAddress((void**)&xp2,  g_xp2);
    cudaGetSymbolAddress((void**)&degA, g_degA);
    cudaGetSymbolAddress((void**)&degL, g_degL);
    cudaGetSymbolAddress((void**)&degR, g_degR);
    cudaGetSymbolAddress((void**)&rowA, g_rowA);
    cudaGetSymbolAddress((void**)&rowL, g_rowL);
    cudaGetSymbolAddress((void**)&rowR, g_rowR);
    cudaGetSymbolAddress((void**)&curA, g_curA);
    cudaGetSymbolAddress((void**)&curL, g_curL);
    cudaGetSymbolAddress((void**)&curR, g_curR);
    cudaGetSymbolAddress((void**)&adjA, g_adjA);
    cudaGetSymbolAddress((void**)&eidL, g_eidL);
    cudaGetSymbolAddress((void**)&eidR, g_eidR);
    cudaGetSymbolAddress((void**)&xph, g_xph);  cudaGetSymbolAddress((void**)&xpl, g_xpl);
    cudaGetSymbolAddress((void**)&h1,  g_h1);
    cudaGetSymbolAddress((void**)&x1h, g_x1h);  cudaGetSymbolAddress((void**)&x1l, g_x1l);
    cudaGetSymbolAddress((void**)&fin, g_fin);
    cudaGetSymbolAddress((void**)&hc,  g_hc);
    cudaGetSymbolAddress((void**)&w1h, g_w1h);  cudaGetSymbolAddress((void**)&w1l, g_w1l);
    cudaGetSymbolAddress((void**)&w2h, g_w2h);  cudaGetSymbolAddress((void**)&w2l, g_w2l);
    cudaGetSymbolAddress((void**)&we2h, g_we2h);
    cudaGetSymbolAddress((void**)&wc1h, g_wc1h);
    cudaGetSymbolAddress((void**)&wc2h, g_wc2h);

    cudaFuncSetAttribute(mma_gemm<3, 0>, cudaFuncAttributeMaxDynamicSharedMemorySize, DSM3);
    cudaFuncSetAttribute(mma_gemm<1, 0>, cudaFuncAttributeMaxDynamicSharedMemorySize, DSM1);
    cudaFuncSetAttribute(mma_gemm<1, 1>, cudaFuncAttributeMaxDynamicSharedMemorySize, DSM1);

    // ===== synapse branch first =====
    fill_int<<<g1((long long)E * 6), 256>>>(xpi, 0x80800000, E * 6);
    synapse_max<<<g1((long long)P * 6), 256>>>(syn, sidx, xpi, P);
    mlp1_fp16<<<g1((long long)E * 128), 256>>>(xpi, We1, be1, h1, E);
    prep_w<<<g1(512LL * 256), 256>>>(We2, we2h, nullptr, 256, 512, 512);
    split_f32<<<g1((long long)N * 64), 256>>>(x_p, xph, xpl, (long long)N * 128);
    {
        dim3 g(4, (E + 127) / 128);
        mma_gemm<1, 1><<<g, 256, DSM1>>>(h1, nullptr, we2h, nullptr, be2, nullptr,
                                         xp2, E, 512, 256, 512, 512, 0);
    }

    // ===== remaining weight prep =====
    prep_w<<<g1(512LL * 128), 256>>>(W1, w1h, w1l, 128, 512, 512);
    prep_w<<<g1(512LL * 512), 256>>>(W2, w2h, w2l, 512, 512, 512);
    prep_w<<<g1(512LL * 1536), 256>>>(Wc1, wc1h, nullptr, 1536, 512, 512);
    prep_w<<<g1(256LL * 512), 256>>>(Wc2, wc2h, nullptr, 512, 256, NCLS);

    // ===== CSR build =====
    fill_int<<<g1(N), 256>>>(degA, 0, N);
    fill_int<<<g1(N), 256>>>(degL, 0, N);
    fill_int<<<g1(N), 256>>>(degR, 0, N);
    count_deg<<<g1(E + N), 256>>>(ei, E, N, degA, degL, degR);
    scan3_kernel<<<3, 1024>>>(degA, rowA, curA, degL, rowL, curL, degR, rowR, curR, N);
    fill_adj<<<g1(E + N), 256>>>(ei, E, N, curA, adjA, curL, eidL, curR, eidR);

    // ===== GAT layer 1 (3-term: attention path stays accurate) =====
    {
        dim3 g(4, (N + 127) / 128);
        mma_gemm<3, 0><<<g, 256, DSM3>>>(xph, xpl, w1h, w1l, nullptr, bufA,
                                         nullptr, N, 512, 128, 512, 512, 0);
    }
    sd_kernel<<<g1((long long)N * 8 * 32), 256>>>(bufA, as1, ad1, s, d, N, 8, 64);
    gat_agg<8, 64, 1><<<N, 256>>>(rowA, adjA, s, d, bufA, b1, x1h, x1l, 512, 1);

    // ===== GAT layer 2 (3-term) =====
    {
        dim3 g(4, (N + 127) / 128);
        mma_gemm<3, 0><<<g, 256, DSM3>>>(x1h, x1l, w2h, w2l, nullptr, bufA,
                                         nullptr, N, 512, 512, 512, 512, 0);
    }
    sd_kernel<<<g1((long long)N * 32), 256>>>(bufA, as2, ad2, s, d, N, 1, 512);
    gat_agg<1, 512, 0><<<N, 256>>>(rowA, adjA, s, d, bufA, b2, fin, nullptr, 1536, 0);

    // ===== scatter means into fin[:,512:1536] =====
    mean_gather2<<<N, 256>>>(rowL, eidL, rowR, eidR, xp2, fin);

    // ===== classifier (1-term fp16) =====
    {
        dim3 g(4, (N + 127) / 128);
        mma_gemm<1, 1><<<g, 256, DSM1>>>(fin, nullptr, wc1h, nullptr, bc1, nullptr,
                                         hc, N, 512, 1536, 512, 512, 1);
    }
    {
        dim3 g(2, (N + 127) / 128);
        mma_gemm<1, 0><<<g, 256, DSM1>>>(hc, nullptr, wc2h, nullptr, bc2, out,
                                         nullptr, N, 256, 512, NCLS, NCLS, 0);
    }
}